// round 13
// baseline (speedup 1.0000x reference)
#include <cuda_runtime.h>
#include <cuda_fp16.h>
#include <cstdint>

#define B_SZ   4096
#define NN     256
#define NA     257
#define KP2H   65536        // W1t row length in halves: 256 i-blocks * 256
#define NPOS   64           // 32 M-blocks x 2 N-blocks
#define TPP    1032         // K-tiles per position: 1024 regular + 8 edge
#define TOTT   (NPOS * TPP) // 66048 total tiles
#define NCTA   296          // 2 per SM, single wave

// ---------------- device-global scratch (no allocation allowed) ----------------
__device__ __align__(256) __half g_W1t[(size_t)NN * KP2H];          // 33.5 MB
__device__ __align__(256) __half g_W1e[(size_t)NN * 512];           // 256 KB edge weights
__device__ __align__(256) float  g_aT [(size_t)256 * B_SZ];         // 4 MB (a transposed, fp32)
__device__ __align__(256) __half g_bh [(size_t)B_SZ * 256];         // 2 MB (b m-major, fp16)
__device__ __align__(256) __half g_eA [(size_t)B_SZ * 512];         // 4 MB (edge A rows, fp16)
__device__ __align__(256) float  g_acc[(size_t)B_SZ * NN];          // 4 MB accumulator

// ---------------- helpers ----------------
static __device__ __forceinline__ uint32_t smem_u32(const void* p) {
    uint32_t a;
    asm("{ .reg .u64 t; cvta.to.shared.u64 t, %1; cvt.u32.u64 %0, t; }" : "=r"(a) : "l"(p));
    return a;
}
static __device__ __forceinline__ void cp16(uint32_t s, const void* g) {
    asm volatile("cp.async.cg.shared.global [%0], [%1], 16;" :: "r"(s), "l"(g));
}
// pack (lo,hi) fp32 -> f16x2 (single final rounding, RN)
static __device__ __forceinline__ uint32_t pkh2(float lo, float hi) {
    uint32_t r;
    asm("cvt.rn.f16x2.f32 %0, %1, %2;" : "=r"(r) : "f"(hi), "f"(lo));
    return r;
}
static __device__ __forceinline__ uint32_t hmul2(uint32_t a, uint32_t b) {
    uint32_t r;
    asm("mul.rn.f16x2 %0, %1, %2;" : "=r"(r) : "r"(a), "r"(b));
    return r;
}
static __device__ __forceinline__ unsigned long long pk1(float x) {
    unsigned long long r;
    asm("mov.b64 %0, {%1, %1};" : "=l"(r) : "f"(x));
    return r;
}
static __device__ __forceinline__ unsigned long long ffma2(
    unsigned long long a, unsigned long long b, unsigned long long c) {
    unsigned long long d;
    asm("fma.rn.f32x2 %0, %1, %2, %3;" : "=l"(d) : "l"(a), "l"(b), "l"(c));
    return d;
}
static __device__ __forceinline__ void upk(unsigned long long v, float& x, float& y) {
    asm("mov.b64 {%0, %1}, %2;" : "=f"(x), "=f"(y) : "l"(v));
}
static __device__ __forceinline__ void ldsm4(uint32_t addr, uint32_t r[4]) {
    asm volatile("ldmatrix.sync.aligned.m8n8.x4.shared.b16 {%0,%1,%2,%3}, [%4];"
                 : "=r"(r[0]), "=r"(r[1]), "=r"(r[2]), "=r"(r[3]) : "r"(addr));
}
static __device__ __forceinline__ void mma_f16(
    float d[4], const uint32_t a[4], const uint32_t b[2]) {
    asm volatile(
        "mma.sync.aligned.m16n8k16.row.col.f32.f16.f16.f32 "
        "{%0,%1,%2,%3}, {%4,%5,%6,%7}, {%8,%9}, {%0,%1,%2,%3};"
        : "+f"(d[0]), "+f"(d[1]), "+f"(d[2]), "+f"(d[3])
        : "r"(a[0]), "r"(a[1]), "r"(a[2]), "r"(a[3]), "r"(b[0]), "r"(b[1]));
}

// ================================================================================
// Pre-pass 0: zero the accumulator (graph-replayed every call)
// ================================================================================
__global__ void __launch_bounds__(256) zero_acc() {
    float4* p = (float4*)g_acc;
    const int idx = blockIdx.x * 256 + threadIdx.x;
#pragma unroll
    for (int q = 0; q < 4; q++)
        p[idx * 4 + q] = make_float4(0.f, 0.f, 0.f, 0.f);
}

// ================================================================================
// Pre-pass 1: transpose inp1 -> g_aT (fp32, [i][m])
// ================================================================================
__global__ void __launch_bounds__(256) prep_aT(const float* __restrict__ in1) {
    __shared__ float tile[32 * 33];
    const int m0 = blockIdx.x * 32, c0 = blockIdx.y * 32;
    const int c = threadIdx.x & 31, r0 = threadIdx.x >> 5;
#pragma unroll
    for (int q = 0; q < 4; q++) {
        int r = r0 + q * 8;
        tile[c * 33 + r] = in1[(size_t)(m0 + r) * 256 + c0 + c];
    }
    __syncthreads();
#pragma unroll
    for (int q = 0; q < 4; q++) {
        int rr = r0 + q * 8;
        g_aT[(size_t)(c0 + rr) * B_SZ + m0 + c] = tile[rr * 33 + c];
    }
}

// ================================================================================
// Pre-pass 1b: m-major fp16 tables.
//   g_bh[m][j]  = fp16(inp2[m][j])
//   g_eA[m][k]  = fp16(inp1[m][k]) k<256 ; 1.0 k==256 ; fp16(inp2[m][k-257]) k>256
// ================================================================================
__global__ void __launch_bounds__(256) prep_h16(
    const float* __restrict__ in1, const float* __restrict__ in2) {
    const int m = blockIdx.x;
    const int t = threadIdx.x;
    const float a = in1[(size_t)m * 256 + t];
    const float b = in2[(size_t)m * 256 + t];
    const __half ha = __float2half_rn(a);
    const __half hb = __float2half_rn(b);
    g_bh[(size_t)m * 256 + t] = hb;
    g_eA[(size_t)m * 512 + t] = ha;
    if (t < 255)  g_eA[(size_t)m * 512 + 257 + t] = hb;   // b[0..254]
    if (t == 255) g_eA[(size_t)m * 512 + 256] = __float2half_rn(1.0f);
}

// ================================================================================
// Pre-pass 2: W1t[n][i*256 + j] = fp16(W1[i*257+j][n]),  i<256, j<256
// ================================================================================
__global__ void __launch_bounds__(256) prep_w1(const float* __restrict__ W1) {
    __shared__ float tile[32 * 33];
    const int i = blockIdx.x, j0 = blockIdx.y * 32, n0 = blockIdx.z * 32;
    const int c = threadIdx.x & 31, r0 = threadIdx.x >> 5;
#pragma unroll
    for (int q = 0; q < 4; q++) {
        int jr = r0 + q * 8;
        size_t k = (size_t)i * NA + j0 + jr;
        tile[c * 33 + jr] = W1[k * NN + n0 + c];
    }
    __syncthreads();
#pragma unroll
    for (int q = 0; q < 4; q++) {
        int nr = r0 + q * 8;
        g_W1t[(size_t)(n0 + nr) * KP2H + (size_t)i * 256 + j0 + c] =
            __float2half_rn(tile[nr * 33 + c]);
    }
}

// ================================================================================
// Pre-pass 3: edge weights. ke<257 -> W1 row ke*257+256 ; 257<=ke<512 -> row
// 65792+(ke-257).  g_W1e[n][ke] = fp16(W1[row(ke)][n]).
// ================================================================================
__global__ void __launch_bounds__(256) prep_w1e(const float* __restrict__ W1) {
    __shared__ float tile[32 * 33];
    const int k0 = blockIdx.x * 32, n0 = blockIdx.y * 32;
    const int c = threadIdx.x & 31, r0 = threadIdx.x >> 5;
#pragma unroll
    for (int q = 0; q < 4; q++) {
        int kr = r0 + q * 8;
        int ke = k0 + kr;
        size_t row = (ke < 257) ? ((size_t)ke * NA + 256)
                                : ((size_t)256 * NA + (ke - 257));
        tile[c * 33 + kr] = W1[row * NN + n0 + c];
    }
    __syncthreads();
#pragma unroll
    for (int q = 0; q < 4; q++) {
        int nr = r0 + q * 8;
        g_W1e[(size_t)(n0 + nr) * 512 + k0 + c] = __float2half_rn(tile[nr * 33 + c]);
    }
}

// ================================================================================
// Main: persistent balanced split-K implicit GEMM, mma.sync fp16 m16n8k16.
// R9 skeleton: 128 threads = 4 warps, warp tile 64x64, depth-2, 296 CTAs (2/SM).
// New: (1) fragment double-buffering across q-steps (ldsm latency hidden under
// HMMA/PREP issue); (2) GENA = 8 LDG.128(g_bh, L1-hot) + 32 HMUL2 + 8 STS.128;
// (3) edge A-tiles are pure cp.async from precomputed g_eA. SMEM 64KB.
// ================================================================================
__global__ void __launch_bounds__(128, 2) mma_main() {
    extern __shared__ __align__(1024) char smem[];
    const uint32_t sbase = smem_u32(smem);
    const uint32_t sA[2] = { sbase,         sbase + 16384 };
    const uint32_t sW[2] = { sbase + 32768, sbase + 49152 };

    const int tid = threadIdx.x;
    const int L   = tid & 31;
    const int wid = tid >> 5;
    const int wm  = wid & 1;    // M half (64 rows)
    const int wn  = wid >> 1;   // N half (64 cols)

    // ldsm lane constants
    const int lsw  = L & 7;
    const int rowA = (L & 7) + ((L >> 3) & 1) * 8;
    const int hiA  = (L >> 4) & 1;
    const int rowB = (L & 7) + ((L >> 4) & 1) * 8;
    const int hiB  = (L >> 3) & 1;
    uint32_t swzA[4], swzB[4], aoff[4], boff[4];
#pragma unroll
    for (int q = 0; q < 4; q++) {
        swzA[q] = ((uint32_t)((2 * q + hiA) ^ lsw)) << 4;
        swzB[q] = ((uint32_t)((2 * q + hiB) ^ lsw)) << 4;
    }
#pragma unroll
    for (int f = 0; f < 4; f++) {
        aoff[f] = (uint32_t)(wm * 64 + f * 16 + rowA) * 128;
        boff[f] = (uint32_t)(wn * 64 + f * 16 + rowB) * 128;
    }

    const uint32_t genO = (uint32_t)tid * 128;
    const uint32_t gsw  = (uint32_t)(tid & 7);
    const uint32_t wO   = (uint32_t)tid * 128;

    float acc[4][8][4];

    // even share of global tiles
    const int start = (int)(((long long)blockIdx.x * TOTT) / NCTA);
    const int end   = (int)(((long long)(blockIdx.x + 1) * TOTT) / NCTA);

// A-gen: 8x (LDG.128 b fp16 row from L1 + 4 HMUL2 + STS.128)
#define GENA(buf_, av2_, jc_) { \
    const char* bsrc__ = bhRow + (jc_) * 128; \
    _Pragma("unroll") \
    for (int w = 0; w < 8; w++) { \
        uint4 bq__ = __ldg((const uint4*)(bsrc__ + w * 16)); \
        uint32_t p0__ = hmul2(bq__.x, av2_); \
        uint32_t p1__ = hmul2(bq__.y, av2_); \
        uint32_t p2__ = hmul2(bq__.z, av2_); \
        uint32_t p3__ = hmul2(bq__.w, av2_); \
        asm volatile("st.shared.v4.b32 [%0], {%1,%2,%3,%4};" \
            :: "r"(sA[buf_] + genO + (((uint32_t)w ^ gsw) << 4)), \
               "r"(p0__), "r"(p1__), "r"(p2__), "r"(p3__) : "memory"); } }

// Edge A-tile: straight cp.async from g_eA (pre-built [a,1,b] fp16 rows)
#define CPAE(buf_, et_) { const __half* src__ = eRowA + (et_) * 64; \
    _Pragma("unroll") \
    for (int w = 0; w < 8; w++) \
        cp16(sA[buf_] + genO + (((uint32_t)w ^ gsw) << 4), src__ + w * 8); }

#define CPW(buf_, i_, jc_) { const __half* src__ = wRow + (size_t)(i_) * 256 + (jc_) * 64; \
    _Pragma("unroll") \
    for (int w = 0; w < 8; w++) \
        cp16(sW[buf_] + wO + (((uint32_t)w ^ gsw) << 4), src__ + w * 8); \
    asm volatile("cp.async.commit_group;"); }

#define CPWE(buf_, et_) { const __half* src__ = eRowW + (et_) * 64; \
    _Pragma("unroll") \
    for (int w = 0; w < 8; w++) \
        cp16(sW[buf_] + wO + (((uint32_t)w ^ gsw) << 4), src__ + w * 8); \
    asm volatile("cp.async.commit_group;"); }

// Prepare tile nt into buffer rb_
#define PREP(rb_, nt_) do { \
    if ((nt_) >= 1024) { CPAE(rb_, (nt_) - 1024); CPWE(rb_, (nt_) - 1024); } \
    else { \
        const int jcn__ = (nt_) >> 8; \
        const uint32_t av2__ = pkh2(av_pf, av_pf); \
        GENA(rb_, av2__, jcn__); \
        CPW(rb_, (nt_) & 255, jcn__); \
    } } while (0)

    int t = start;
    while (t < end) {
        const int pos = t / TPP;
        const int pend = (pos + 1) * TPP < end ? (pos + 1) * TPP : end;
        const int ls = t - pos * TPP;
        const int le = pend - pos * TPP;
        const int m0 = (pos >> 1) * 128;
        const int n0 = (pos & 1) * 128;

        const float*  aTb   = g_aT + m0 + tid;
        const char*   bhRow = (const char*)g_bh + (size_t)(m0 + tid) * 512;
        const __half* eRowA = g_eA + (size_t)(m0 + tid) * 512;
        const __half* wRow  = g_W1t + (size_t)(n0 + tid) * KP2H;
        const __half* eRowW = g_W1e + (size_t)(n0 + tid) * 512;

#pragma unroll
        for (int mf = 0; mf < 4; mf++)
#pragma unroll
            for (int nf = 0; nf < 8; nf++)
#pragma unroll
                for (int e = 0; e < 4; e++) acc[mf][nf][e] = 0.0f;

        __syncthreads();  // protect buffers from lagging warps of prev segment

        // prologue: tile ls into buffer 0
        float av_pf = 0.0f;
        if (ls < 1024) av_pf = __ldg(aTb + (size_t)(ls & 255) * B_SZ);
        PREP(0, ls);
        if (ls + 1 < le && ls + 1 < 1024)
            av_pf = __ldg(aTb + (size_t)((ls + 1) & 255) * B_SZ);

        int buf = 0;
        for (int T = ls; T < le; T++) {
            asm volatile("cp.async.wait_group 0;");
            __syncthreads();

            // q0 fragment prefetch (latency hides under PREP below)
            uint32_t afr[2][4][4], bfr[2][4][4];
#pragma unroll
            for (int mf = 0; mf < 4; mf++)
                ldsm4(sA[buf] + aoff[mf] + swzA[0], afr[0][mf]);
#pragma unroll
            for (int n2 = 0; n2 < 4; n2++)
                ldsm4(sW[buf] + boff[n2] + swzB[0], bfr[0][n2]);

            if (T + 1 < le) {
                PREP(buf ^ 1, T + 1);
                if (T + 2 < le && T + 2 < 1024)
                    av_pf = __ldg(aTb + (size_t)((T + 2) & 255) * B_SZ);
            }

            // software-pipelined MMA: ldsm(q+1) issues before HMMA(q)
#pragma unroll
            for (int q = 0; q < 4; q++) {
                const int cur = q & 1, nxt = cur ^ 1;
                if (q < 3) {
#pragma unroll
                    for (int mf = 0; mf < 4; mf++)
                        ldsm4(sA[buf] + aoff[mf] + swzA[q + 1], afr[nxt][mf]);
#pragma unroll
                    for (int n2 = 0; n2 < 4; n2++)
                        ldsm4(sW[buf] + boff[n2] + swzB[q + 1], bfr[nxt][n2]);
                }
#pragma unroll
                for (int mf = 0; mf < 4; mf++)
#pragma unroll
                    for (int nf = 0; nf < 8; nf++)
                        mma_f16(acc[mf][nf], afr[cur][mf], &bfr[cur][nf >> 1][(nf & 1) * 2]);
            }
            buf ^= 1;
        }

        // flush this position's contribution (RED)
#pragma unroll
        for (int mf = 0; mf < 4; mf++) {
            const int gm = m0 + wm * 64 + mf * 16 + (L >> 2);
#pragma unroll
            for (int nf = 0; nf < 8; nf++) {
                const int gn = n0 + wn * 64 + nf * 8 + 2 * (L & 3);
                float* p0 = g_acc + (size_t)gm * NN + gn;
                float* p1 = g_acc + (size_t)(gm + 8) * NN + gn;
                atomicAdd(p0,     acc[mf][nf][0]);
                atomicAdd(p0 + 1, acc[mf][nf][1]);
                atomicAdd(p1,     acc[mf][nf][2]);
                atomicAdd(p1 + 1, acc[mf][nf][3]);
            }
        }

        t = pend;
    }
}

// ================================================================================
// Reduce: g_acc + leftover edge column (ke=512 -> i=256,j=255) + b1 + relu -> h,
// then layer2 FFMA2 + b2 + relu
// ================================================================================
__global__ void __launch_bounds__(256) reduce_l2(
    const float* __restrict__ inp2, const float* __restrict__ W1,
    const float* __restrict__ b1, const float* __restrict__ W2,
    const float* __restrict__ b2, float* __restrict__ out) {
    __shared__ float h_t[256 * 34];  // h transposed: h_t[k][m], stride 34
    const int m0 = blockIdx.x * 32;
    const int n  = threadIdx.x;

    const float bb1 = __ldg(b1 + n);
    // leftover edge term: fusion[m, 256*257+255] = b[m,255]; weight row 66047
    const float wlast = __ldg(W1 + (size_t)66047 * NN + n);
#pragma unroll 4
    for (int q = 0; q < 32; q++) {
        const float blast = __ldg(inp2 + (size_t)(m0 + q) * 256 + 255);
        float sum = fmaf(blast, wlast, bb1) + g_acc[(size_t)(m0 + q) * NN + n];
        h_t[n * 34 + q] = fmaxf(sum, 0.0f);
    }
    __syncthreads();

    unsigned long long acc[16];
#pragma unroll
    for (int mp = 0; mp < 16; mp++) acc[mp] = 0ull;

#pragma unroll 4
    for (int k = 0; k < NN; k++) {
        const unsigned long long wp = pk1(__ldg(W2 + (size_t)k * NN + n));
        const float* hk = &h_t[k * 34];
#pragma unroll
        for (int mp = 0; mp < 16; mp++) {
            unsigned long long hv = *(const unsigned long long*)(hk + 2 * mp);
            acc[mp] = ffma2(hv, wp, acc[mp]);
        }
    }

    const float bb2 = __ldg(b2 + n);
#pragma unroll
    for (int mp = 0; mp < 16; mp++) {
        float x, y;
        upk(acc[mp], x, y);
        out[(size_t)(m0 + 2 * mp) * NN + n]     = fmaxf(x + bb2, 0.0f);
        out[(size_t)(m0 + 2 * mp + 1) * NN + n] = fmaxf(y + bb2, 0.0f);
    }
}

// ================================================================================
extern "C" void kernel_launch(void* const* d_in, const int* in_sizes, int n_in,
                              void* d_out, int out_size) {
    const float* inp1 = (const float*)d_in[0];
    const float* inp2 = (const float*)d_in[1];
    const float* W1   = (const float*)d_in[2];
    const float* b1   = (const float*)d_in[3];
    const float* W2   = (const float*)d_in[4];
    const float* b2   = (const float*)d_in[5];
    float* out = (float*)d_out;

    cudaFuncSetAttribute(mma_main, cudaFuncAttributeMaxDynamicSharedMemorySize, 65536);

    zero_acc<<<B_SZ * NN / (256 * 16), 256>>>();
    prep_aT<<<dim3(128, 8), 256>>>(inp1);
    prep_h16<<<B_SZ, 256>>>(inp1, inp2);
    prep_w1<<<dim3(256, 8, 8), 256>>>(W1);
    prep_w1e<<<dim3(16, 8), 256>>>(W1);
    mma_main<<<NCTA, 128, 65536>>>();
    reduce_l2<<<B_SZ / 32, 256>>>(inp2, W1, b1, W2, b2, out);
}

// round 14
// speedup vs baseline: 1.1841x; 1.1841x over previous
#include <cuda_runtime.h>
#include <cuda_fp16.h>
#include <cstdint>

#define B_SZ   4096
#define NN     256
#define NA     257
#define KP2H   65536        // W1t row length in halves: 256 i-blocks * 256
#define NPOS   64           // 32 M-blocks x 2 N-blocks
#define TPP    1032         // K-tiles per position: 1024 regular + 8 edge
#define TOTT   (NPOS * TPP) // 66048 total tiles
#define NCTA   296          // 2 per SM, single wave

// ---------------- device-global scratch (no allocation allowed) ----------------
__device__ __align__(256) __half g_W1t[(size_t)NN * KP2H];          // 33.5 MB
__device__ __align__(256) __half g_W1e[(size_t)NN * 512];           // 256 KB edge weights
__device__ __align__(256) float  g_aT [(size_t)256 * B_SZ];         // 4 MB (a transposed, fp32)
__device__ __align__(256) __half g_bh [(size_t)B_SZ * 256];         // 2 MB (b m-major, fp16)
__device__ __align__(256) __half g_eA [(size_t)B_SZ * 512];         // 4 MB (edge A rows, fp16)
__device__ __align__(256) float  g_acc[(size_t)B_SZ * NN];          // 4 MB accumulator

// ---------------- helpers ----------------
static __device__ __forceinline__ uint32_t smem_u32(const void* p) {
    uint32_t a;
    asm("{ .reg .u64 t; cvta.to.shared.u64 t, %1; cvt.u32.u64 %0, t; }" : "=r"(a) : "l"(p));
    return a;
}
static __device__ __forceinline__ void cp16(uint32_t s, const void* g) {
    asm volatile("cp.async.cg.shared.global [%0], [%1], 16;" :: "r"(s), "l"(g));
}
// pack (lo,hi) fp32 -> f16x2 (single final rounding, RN)
static __device__ __forceinline__ uint32_t pkh2(float lo, float hi) {
    uint32_t r;
    asm("cvt.rn.f16x2.f32 %0, %1, %2;" : "=r"(r) : "f"(hi), "f"(lo));
    return r;
}
static __device__ __forceinline__ uint32_t hmul2(uint32_t a, uint32_t b) {
    uint32_t r;
    asm("mul.rn.f16x2 %0, %1, %2;" : "=r"(r) : "r"(a), "r"(b));
    return r;
}
static __device__ __forceinline__ unsigned long long pk1(float x) {
    unsigned long long r;
    asm("mov.b64 %0, {%1, %1};" : "=l"(r) : "f"(x));
    return r;
}
static __device__ __forceinline__ unsigned long long ffma2(
    unsigned long long a, unsigned long long b, unsigned long long c) {
    unsigned long long d;
    asm("fma.rn.f32x2 %0, %1, %2, %3;" : "=l"(d) : "l"(a), "l"(b), "l"(c));
    return d;
}
static __device__ __forceinline__ void upk(unsigned long long v, float& x, float& y) {
    asm("mov.b64 {%0, %1}, %2;" : "=f"(x), "=f"(y) : "l"(v));
}
static __device__ __forceinline__ void ldsm4(uint32_t addr, uint32_t r[4]) {
    asm volatile("ldmatrix.sync.aligned.m8n8.x4.shared.b16 {%0,%1,%2,%3}, [%4];"
                 : "=r"(r[0]), "=r"(r[1]), "=r"(r[2]), "=r"(r[3]) : "r"(addr));
}
static __device__ __forceinline__ void mma_f16(
    float d[4], const uint32_t a[4], const uint32_t b[2]) {
    asm volatile(
        "mma.sync.aligned.m16n8k16.row.col.f32.f16.f16.f32 "
        "{%0,%1,%2,%3}, {%4,%5,%6,%7}, {%8,%9}, {%0,%1,%2,%3};"
        : "+f"(d[0]), "+f"(d[1]), "+f"(d[2]), "+f"(d[3])
        : "r"(a[0]), "r"(a[1]), "r"(a[2]), "r"(a[3]), "r"(b[0]), "r"(b[1]));
}

// ================================================================================
// Pre-pass 0: zero the accumulator (graph-replayed every call)
// ================================================================================
__global__ void __launch_bounds__(256) zero_acc() {
    float4* p = (float4*)g_acc;
    const int idx = blockIdx.x * 256 + threadIdx.x;
#pragma unroll
    for (int q = 0; q < 4; q++)
        p[idx * 4 + q] = make_float4(0.f, 0.f, 0.f, 0.f);
}

// ================================================================================
// Pre-pass 1: transpose inp1 -> g_aT (fp32, [i][m])
// ================================================================================
__global__ void __launch_bounds__(256) prep_aT(const float* __restrict__ in1) {
    __shared__ float tile[32 * 33];
    const int m0 = blockIdx.x * 32, c0 = blockIdx.y * 32;
    const int c = threadIdx.x & 31, r0 = threadIdx.x >> 5;
#pragma unroll
    for (int q = 0; q < 4; q++) {
        int r = r0 + q * 8;
        tile[c * 33 + r] = in1[(size_t)(m0 + r) * 256 + c0 + c];
    }
    __syncthreads();
#pragma unroll
    for (int q = 0; q < 4; q++) {
        int rr = r0 + q * 8;
        g_aT[(size_t)(c0 + rr) * B_SZ + m0 + c] = tile[rr * 33 + c];
    }
}

// ================================================================================
// Pre-pass 1b: m-major fp16 tables.
//   g_bh[m][j]  = fp16(inp2[m][j])
//   g_eA[m][k]  = fp16(inp1[m][k]) k<256 ; 1.0 k==256 ; fp16(inp2[m][k-257]) k>256
// ================================================================================
__global__ void __launch_bounds__(256) prep_h16(
    const float* __restrict__ in1, const float* __restrict__ in2) {
    const int m = blockIdx.x;
    const int t = threadIdx.x;
    const float a = in1[(size_t)m * 256 + t];
    const float b = in2[(size_t)m * 256 + t];
    const __half ha = __float2half_rn(a);
    const __half hb = __float2half_rn(b);
    g_bh[(size_t)m * 256 + t] = hb;
    g_eA[(size_t)m * 512 + t] = ha;
    if (t < 255)  g_eA[(size_t)m * 512 + 257 + t] = hb;   // b[0..254]
    if (t == 255) g_eA[(size_t)m * 512 + 256] = __float2half_rn(1.0f);
}

// ================================================================================
// Pre-pass 2: W1t[n][i*256 + j] = fp16(W1[i*257+j][n]),  i<256, j<256
// ================================================================================
__global__ void __launch_bounds__(256) prep_w1(const float* __restrict__ W1) {
    __shared__ float tile[32 * 33];
    const int i = blockIdx.x, j0 = blockIdx.y * 32, n0 = blockIdx.z * 32;
    const int c = threadIdx.x & 31, r0 = threadIdx.x >> 5;
#pragma unroll
    for (int q = 0; q < 4; q++) {
        int jr = r0 + q * 8;
        size_t k = (size_t)i * NA + j0 + jr;
        tile[c * 33 + jr] = W1[k * NN + n0 + c];
    }
    __syncthreads();
#pragma unroll
    for (int q = 0; q < 4; q++) {
        int nr = r0 + q * 8;
        g_W1t[(size_t)(n0 + nr) * KP2H + (size_t)i * 256 + j0 + c] =
            __float2half_rn(tile[nr * 33 + c]);
    }
}

// ================================================================================
// Pre-pass 3: edge weights. ke<257 -> W1 row ke*257+256 ; 257<=ke<512 -> row
// 65792+(ke-257).  g_W1e[n][ke] = fp16(W1[row(ke)][n]).
// ================================================================================
__global__ void __launch_bounds__(256) prep_w1e(const float* __restrict__ W1) {
    __shared__ float tile[32 * 33];
    const int k0 = blockIdx.x * 32, n0 = blockIdx.y * 32;
    const int c = threadIdx.x & 31, r0 = threadIdx.x >> 5;
#pragma unroll
    for (int q = 0; q < 4; q++) {
        int kr = r0 + q * 8;
        int ke = k0 + kr;
        size_t row = (ke < 257) ? ((size_t)ke * NA + 256)
                                : ((size_t)256 * NA + (ke - 257));
        tile[c * 33 + kr] = W1[row * NN + n0 + c];
    }
    __syncthreads();
#pragma unroll
    for (int q = 0; q < 4; q++) {
        int nr = r0 + q * 8;
        g_W1e[(size_t)(n0 + nr) * 512 + k0 + c] = __float2half_rn(tile[nr * 33 + c]);
    }
}

// ================================================================================
// Main: persistent balanced split-K implicit GEMM, mma.sync fp16 m16n8k16.
// R9 skeleton (128 thr = 4 warps, warp tile 64x64, 296 CTAs = 2/SM), but the
// A-tile is NEVER materialized: b[m][jc*64..] is staged in SMEM once per jc
// (256 tiles), ldsm'd per tile with A-fragment layout, and A-frag = hmul2(bfrag,
// a2(row)) in registers (rank-1 structure). Edge tiles: cp.async g_eA, a2 = 1.
// SMEM 64KB: sB(16K, doubles as edge-A buf0) sE1(16K) sW0 sW1.
// ================================================================================
__global__ void __launch_bounds__(128, 2) mma_main() {
    extern __shared__ __align__(1024) char smem[];
    const uint32_t sbase = smem_u32(smem);
    const uint32_t sB    = sbase;
    const uint32_t sE1   = sbase + 16384;
    const uint32_t sW[2] = { sbase + 32768, sbase + 49152 };

    const int tid = threadIdx.x;
    const int L   = tid & 31;
    const int wid = tid >> 5;
    const int wm  = wid & 1;    // M half (64 rows)
    const int wn  = wid >> 1;   // N half (64 cols)

    // ldsm lane constants
    const int lsw  = L & 7;
    const int rowA = (L & 7) + ((L >> 3) & 1) * 8;
    const int hiA  = (L >> 4) & 1;
    const int rowB = (L & 7) + ((L >> 4) & 1) * 8;
    const int hiB  = (L >> 3) & 1;
    uint32_t swzA[4], swzB[4], aoff[4], boff[4];
#pragma unroll
    for (int q = 0; q < 4; q++) {
        swzA[q] = ((uint32_t)((2 * q + hiA) ^ lsw)) << 4;
        swzB[q] = ((uint32_t)((2 * q + hiB) ^ lsw)) << 4;
    }
#pragma unroll
    for (int f = 0; f < 4; f++) {
        aoff[f] = (uint32_t)(wm * 64 + f * 16 + rowA) * 128;
        boff[f] = (uint32_t)(wn * 64 + f * 16 + rowB) * 128;
    }

    const uint32_t genO = (uint32_t)tid * 128;
    const uint32_t gsw  = (uint32_t)(tid & 7);
    const uint32_t wO   = (uint32_t)tid * 128;

    float acc[4][8][4];

    // even share of global tiles
    const int start = (int)(((long long)blockIdx.x * TOTT) / NCTA);
    const int end   = (int)(((long long)(blockIdx.x + 1) * TOTT) / NCTA);

// Stage b[m][jc*64..+63] fp16 into sB (swizzled rows), rides next commit group
#define STAGEB(jc_) { const char* bsrc__ = bhRow + (jc_) * 128; \
    _Pragma("unroll") \
    for (int w = 0; w < 8; w++) \
        cp16(sB + genO + (((uint32_t)w ^ gsw) << 4), bsrc__ + w * 16); }

// Edge A-tile: straight cp.async from g_eA (pre-built [a,1,b] fp16 rows)
#define CPAE(dst_, et_) { const __half* src__ = eRowA + (et_) * 64; \
    _Pragma("unroll") \
    for (int w = 0; w < 8; w++) \
        cp16((dst_) + genO + (((uint32_t)w ^ gsw) << 4), src__ + w * 8); }

#define CPW(buf_, i_, jc_) { const __half* src__ = wRow + (size_t)(i_) * 256 + (jc_) * 64; \
    _Pragma("unroll") \
    for (int w = 0; w < 8; w++) \
        cp16(sW[buf_] + wO + (((uint32_t)w ^ gsw) << 4), src__ + w * 8); \
    asm volatile("cp.async.commit_group;"); }

#define CPWE(buf_, et_) { const __half* src__ = eRowW + (et_) * 64; \
    _Pragma("unroll") \
    for (int w = 0; w < 8; w++) \
        cp16(sW[buf_] + wO + (((uint32_t)w ^ gsw) << 4), src__ + w * 8); \
    asm volatile("cp.async.commit_group;"); }

// Prefetch a[i][rows] (8 broadcast LDG.32, L1-hot)
#define LDA(i_) { const float* ap__ = g_aT + (size_t)(i_) * B_SZ + m0 + wm * 64 + (L >> 2); \
    _Pragma("unroll") \
    for (int mf = 0; mf < 4; mf++) { \
        a_pf[2 * mf]     = __ldg(ap__ + mf * 16); \
        a_pf[2 * mf + 1] = __ldg(ap__ + mf * 16 + 8); } }

// One K-tile of MMA: ldsm b with A-frag layout, afr = hmul2(bfrag, a2), HMMA.
// Frag reg mapping: regs 0,2 -> row r (a2lo); regs 1,3 -> row r+8 (a2hi).
#define MMA_TILE(abase_, wbuf_) { \
    _Pragma("unroll") \
    for (int q = 0; q < 4; q++) { \
        uint32_t afr[4][4], bfr[4][4]; \
        _Pragma("unroll") \
        for (int mf = 0; mf < 4; mf++) \
            ldsm4((abase_) + aoff[mf] + swzA[q], afr[mf]); \
        _Pragma("unroll") \
        for (int n2 = 0; n2 < 4; n2++) \
            ldsm4(sW[wbuf_] + boff[n2] + swzB[q], bfr[n2]); \
        _Pragma("unroll") \
        for (int mf = 0; mf < 4; mf++) { \
            afr[mf][0] = hmul2(afr[mf][0], a2lo[mf]); \
            afr[mf][1] = hmul2(afr[mf][1], a2hi[mf]); \
            afr[mf][2] = hmul2(afr[mf][2], a2lo[mf]); \
            afr[mf][3] = hmul2(afr[mf][3], a2hi[mf]); } \
        _Pragma("unroll") \
        for (int mf = 0; mf < 4; mf++) \
            _Pragma("unroll") \
            for (int nf = 0; nf < 8; nf++) \
                mma_f16(acc[mf][nf], afr[mf], &bfr[nf >> 1][(nf & 1) * 2]); } }

    int t = start;
    while (t < end) {
        const int pos = t / TPP;
        const int pend = (pos + 1) * TPP < end ? (pos + 1) * TPP : end;
        const int ls = t - pos * TPP;
        const int le = pend - pos * TPP;
        const int m0 = (pos >> 1) * 128;
        const int n0 = (pos & 1) * 128;

        const char*   bhRow = (const char*)g_bh + (size_t)(m0 + tid) * 512;
        const __half* eRowA = g_eA + (size_t)(m0 + tid) * 512;
        const __half* wRow  = g_W1t + (size_t)(n0 + tid) * KP2H;
        const __half* eRowW = g_W1e + (size_t)(n0 + tid) * 512;

#pragma unroll
        for (int mf = 0; mf < 4; mf++)
#pragma unroll
            for (int nf = 0; nf < 8; nf++)
#pragma unroll
                for (int e = 0; e < 4; e++) acc[mf][nf][e] = 0.0f;

        // ---- regular tiles, grouped by jc (b-tile static per group) ----
        const int regEnd = le < 1024 ? le : 1024;
        int T0 = ls;
        while (T0 < regEnd) {
            const int jc = T0 >> 8;
            int T1 = (jc + 1) * 256;
            if (T1 > regEnd) T1 = regEnd;

            __syncthreads();            // sB / sW safe to rewrite
            STAGEB(jc);
            CPW(0, T0 & 255, jc);       // stage_b rides this commit group
            float a_pf[8];
            LDA(T0 & 255);

            int buf = 0;
            for (int T = T0; T < T1; T++) {
                asm volatile("cp.async.wait_group 0;");
                __syncthreads();

                uint32_t a2lo[4], a2hi[4];
#pragma unroll
                for (int mf = 0; mf < 4; mf++) {
                    a2lo[mf] = pkh2(a_pf[2 * mf],     a_pf[2 * mf]);
                    a2hi[mf] = pkh2(a_pf[2 * mf + 1], a_pf[2 * mf + 1]);
                }
                if (T + 1 < T1) {
                    CPW(buf ^ 1, (T + 1) & 255, jc);
                    LDA((T + 1) & 255);
                }
                MMA_TILE(sB, buf);
                buf ^= 1;
            }
            T0 = T1;
        }

        // ---- edge tiles (a2 = 1.0), A double-buffered in sB / sE1 ----
        if (le > 1024) {
            const int E0 = ls > 1024 ? ls : 1024;
            uint32_t a2lo[4], a2hi[4];
#pragma unroll
            for (int mf = 0; mf < 4; mf++) { a2lo[mf] = 0x3C003C00u; a2hi[mf] = 0x3C003C00u; }

            __syncthreads();
            CPAE(sB, E0 - 1024);
            CPWE(0, E0 - 1024);
            int buf = 0;
            for (int T = E0; T < le; T++) {
                asm volatile("cp.async.wait_group 0;");
                __syncthreads();
                if (T + 1 < le) {
                    CPAE(buf ? sB : sE1, T + 1 - 1024);
                    CPWE(buf ^ 1, T + 1 - 1024);
                }
                MMA_TILE(buf ? sE1 : sB, buf);
                buf ^= 1;
            }
        }

        // flush this position's contribution (RED)
#pragma unroll
        for (int mf = 0; mf < 4; mf++) {
            const int gm = m0 + wm * 64 + mf * 16 + (L >> 2);
#pragma unroll
            for (int nf = 0; nf < 8; nf++) {
                const int gn = n0 + wn * 64 + nf * 8 + 2 * (L & 3);
                float* p0 = g_acc + (size_t)gm * NN + gn;
                float* p1 = g_acc + (size_t)(gm + 8) * NN + gn;
                atomicAdd(p0,     acc[mf][nf][0]);
                atomicAdd(p0 + 1, acc[mf][nf][1]);
                atomicAdd(p1,     acc[mf][nf][2]);
                atomicAdd(p1 + 1, acc[mf][nf][3]);
            }
        }

        t = pend;
    }
}

// ================================================================================
// Reduce: g_acc + leftover edge column (ke=512 -> i=256,j=255) + b1 + relu -> h,
// then layer2 FFMA2 + b2 + relu
// ================================================================================
__global__ void __launch_bounds__(256) reduce_l2(
    const float* __restrict__ inp2, const float* __restrict__ W1,
    const float* __restrict__ b1, const float* __restrict__ W2,
    const float* __restrict__ b2, float* __restrict__ out) {
    __shared__ float h_t[256 * 34];  // h transposed: h_t[k][m], stride 34
    const int m0 = blockIdx.x * 32;
    const int n  = threadIdx.x;

    const float bb1 = __ldg(b1 + n);
    // leftover edge term: fusion[m, 256*257+255] = b[m,255]; weight row 66047
    const float wlast = __ldg(W1 + (size_t)66047 * NN + n);
#pragma unroll 4
    for (int q = 0; q < 32; q++) {
        const float blast = __ldg(inp2 + (size_t)(m0 + q) * 256 + 255);
        float sum = fmaf(blast, wlast, bb1) + g_acc[(size_t)(m0 + q) * NN + n];
        h_t[n * 34 + q] = fmaxf(sum, 0.0f);
    }
    __syncthreads();

    unsigned long long acc[16];
#pragma unroll
    for (int mp = 0; mp < 16; mp++) acc[mp] = 0ull;

#pragma unroll 4
    for (int k = 0; k < NN; k++) {
        const unsigned long long wp = pk1(__ldg(W2 + (size_t)k * NN + n));
        const float* hk = &h_t[k * 34];
#pragma unroll
        for (int mp = 0; mp < 16; mp++) {
            unsigned long long hv = *(const unsigned long long*)(hk + 2 * mp);
            acc[mp] = ffma2(hv, wp, acc[mp]);
        }
    }

    const float bb2 = __ldg(b2 + n);
#pragma unroll
    for (int mp = 0; mp < 16; mp++) {
        float x, y;
        upk(acc[mp], x, y);
        out[(size_t)(m0 + 2 * mp) * NN + n]     = fmaxf(x + bb2, 0.0f);
        out[(size_t)(m0 + 2 * mp + 1) * NN + n] = fmaxf(y + bb2, 0.0f);
    }
}

// ================================================================================
extern "C" void kernel_launch(void* const* d_in, const int* in_sizes, int n_in,
                              void* d_out, int out_size) {
    const float* inp1 = (const float*)d_in[0];
    const float* inp2 = (const float*)d_in[1];
    const float* W1   = (const float*)d_in[2];
    const float* b1   = (const float*)d_in[3];
    const float* W2   = (const float*)d_in[4];
    const float* b2   = (const float*)d_in[5];
    float* out = (float*)d_out;

    cudaFuncSetAttribute(mma_main, cudaFuncAttributeMaxDynamicSharedMemorySize, 65536);

    zero_acc<<<B_SZ * NN / (256 * 16), 256>>>();
    prep_aT<<<dim3(128, 8), 256>>>(inp1);
    prep_h16<<<B_SZ, 256>>>(inp1, inp2);
    prep_w1<<<dim3(256, 8, 8), 256>>>(W1);
    prep_w1e<<<dim3(16, 8), 256>>>(W1);
    mma_main<<<NCTA, 128, 65536>>>();
    reduce_l2<<<B_SZ / 32, 256>>>(inp2, W1, b1, W2, b2, out);
}

// round 15
// speedup vs baseline: 1.2375x; 1.0451x over previous
#include <cuda_runtime.h>
#include <cuda_fp16.h>
#include <cstdint>

#define B_SZ   4096
#define NN     256
#define NA     257
#define KP2H   65536        // W1t row length in halves: 256 i-blocks * 256
#define NPOS   64           // 32 M-blocks x 2 N-blocks
#define TPP    1032         // K-tiles per position: 1024 regular + 8 edge
#define TOTT   (NPOS * TPP) // 66048 total tiles
#define NCTA   296          // 2 per SM, single wave

// ---------------- device-global scratch (no allocation allowed) ----------------
__device__ __align__(256) __half g_W1t[(size_t)NN * KP2H];          // 33.5 MB
__device__ __align__(256) __half g_W1e[(size_t)NN * 512];           // 256 KB edge weights
__device__ __align__(256) float g_aT [(size_t)256 * B_SZ];          // 4 MB
__device__ __align__(256) float g_bT [(size_t)256 * B_SZ];          // 4 MB
__device__ __align__(256) float g_acc[(size_t)B_SZ * NN];           // 4 MB accumulator

// ---------------- helpers ----------------
static __device__ __forceinline__ uint32_t smem_u32(const void* p) {
    uint32_t a;
    asm("{ .reg .u64 t; cvta.to.shared.u64 t, %1; cvt.u32.u64 %0, t; }" : "=r"(a) : "l"(p));
    return a;
}
static __device__ __forceinline__ void cp16(uint32_t s, const void* g) {
    asm volatile("cp.async.cg.shared.global [%0], [%1], 16;" :: "r"(s), "l"(g));
}
// pack (lo,hi) fp32 -> f16x2 (single final rounding, RN)
static __device__ __forceinline__ uint32_t pkh2(float lo, float hi) {
    uint32_t r;
    asm("cvt.rn.f16x2.f32 %0, %1, %2;" : "=r"(r) : "f"(hi), "f"(lo));
    return r;
}
static __device__ __forceinline__ unsigned long long pk1(float x) {
    unsigned long long r;
    asm("mov.b64 %0, {%1, %1};" : "=l"(r) : "f"(x));
    return r;
}
static __device__ __forceinline__ unsigned long long ffma2(
    unsigned long long a, unsigned long long b, unsigned long long c) {
    unsigned long long d;
    asm("fma.rn.f32x2 %0, %1, %2, %3;" : "=l"(d) : "l"(a), "l"(b), "l"(c));
    return d;
}
static __device__ __forceinline__ void upk(unsigned long long v, float& x, float& y) {
    asm("mov.b64 {%0, %1}, %2;" : "=f"(x), "=f"(y) : "l"(v));
}
static __device__ __forceinline__ void ldsm4(uint32_t addr, uint32_t r[4]) {
    asm volatile("ldmatrix.sync.aligned.m8n8.x4.shared.b16 {%0,%1,%2,%3}, [%4];"
                 : "=r"(r[0]), "=r"(r[1]), "=r"(r[2]), "=r"(r[3]) : "r"(addr));
}
static __device__ __forceinline__ void mma_f16(
    float d[4], const uint32_t a[4], const uint32_t b[2]) {
    asm volatile(
        "mma.sync.aligned.m16n8k16.row.col.f32.f16.f16.f32 "
        "{%0,%1,%2,%3}, {%4,%5,%6,%7}, {%8,%9}, {%0,%1,%2,%3};"
        : "+f"(d[0]), "+f"(d[1]), "+f"(d[2]), "+f"(d[3])
        : "r"(a[0]), "r"(a[1]), "r"(a[2]), "r"(a[3]), "r"(b[0]), "r"(b[1]));
}

// ================================================================================
// Pre-pass 1: transpose inp1 / inp2 -> g_aT / g_bT (fp32) + zero g_acc (merged)
// ================================================================================
__global__ void __launch_bounds__(256) prep_inputs(
    const float* __restrict__ in1, const float* __restrict__ in2) {
    __shared__ float tile[32 * 33];
    const float* src = blockIdx.z ? in2 : in1;
    float* dst = blockIdx.z ? g_bT : g_aT;
    const int m0 = blockIdx.x * 32, c0 = blockIdx.y * 32;
    const int c = threadIdx.x & 31, r0 = threadIdx.x >> 5;

    // merged accumulator zeroing: 2048 blocks x 256 thr x 1 float2 = 1M floats
    {
        const int bid = (blockIdx.z * gridDim.y + blockIdx.y) * gridDim.x + blockIdx.x;
        const int idx = bid * 256 + threadIdx.x;
        ((float2*)g_acc)[idx] = make_float2(0.f, 0.f);
    }

#pragma unroll
    for (int q = 0; q < 4; q++) {
        int r = r0 + q * 8;
        tile[c * 33 + r] = src[(size_t)(m0 + r) * 256 + c0 + c];
    }
    __syncthreads();
#pragma unroll
    for (int q = 0; q < 4; q++) {
        int rr = r0 + q * 8;
        dst[(size_t)(c0 + rr) * B_SZ + m0 + c] = tile[rr * 33 + c];
    }
}

// ================================================================================
// Pre-pass 2: W1t[n][i*256 + j] = fp16(W1[i*257+j][n]),  i<256, j<256
// Retiled 64j x 32n so fp16 writes are full 128B/warp. grid (256, 4, 8).
// ================================================================================
__global__ void __launch_bounds__(256) prep_w1(const float* __restrict__ W1) {
    __shared__ float tile[64 * 33];   // [j][n], padded
    const int i  = blockIdx.x;
    const int j0 = blockIdx.y * 64;
    const int n0 = blockIdx.z * 32;
    const int tid = threadIdx.x;
    const int c = tid & 31, r0 = tid >> 5;
#pragma unroll
    for (int q = 0; q < 8; q++) {
        int j = r0 + q * 8;
        tile[j * 33 + c] = W1[((size_t)i * NA + j0 + j) * NN + n0 + c];
    }
    __syncthreads();
    uint32_t* dst32 = (uint32_t*)g_W1t;
#pragma unroll
    for (int q = 0; q < 4; q++) {
        int e = tid + q * 256;
        int n  = e >> 5;          // 0..31
        int jj = e & 31;          // u32 (2 halves) within the 64-j chunk
        float lo = tile[(2 * jj)     * 33 + n];
        float hi = tile[(2 * jj + 1) * 33 + n];
        dst32[(((size_t)(n0 + n) * KP2H + (size_t)i * 256 + j0) >> 1) + jj] = pkh2(lo, hi);
    }
}

// ================================================================================
// Pre-pass 3: edge weights. ke<257 -> W1 row ke*257+256 ; 257<=ke<512 -> row
// 65792+(ke-257).  g_W1e[n][ke] = fp16(W1[row(ke)][n]).
// ================================================================================
__global__ void __launch_bounds__(256) prep_w1e(const float* __restrict__ W1) {
    __shared__ float tile[32 * 33];
    const int k0 = blockIdx.x * 32, n0 = blockIdx.y * 32;
    const int c = threadIdx.x & 31, r0 = threadIdx.x >> 5;
#pragma unroll
    for (int q = 0; q < 4; q++) {
        int kr = r0 + q * 8;
        int ke = k0 + kr;
        size_t row = (ke < 257) ? ((size_t)ke * NA + 256)
                                : ((size_t)256 * NA + (ke - 257));
        tile[c * 33 + kr] = W1[row * NN + n0 + c];
    }
    __syncthreads();
#pragma unroll
    for (int q = 0; q < 4; q++) {
        int nr = r0 + q * 8;
        g_W1e[(size_t)(n0 + nr) * 512 + k0 + c] = __float2half_rn(tile[nr * 33 + c]);
    }
}

// ================================================================================
// Main: persistent balanced split-K implicit GEMM, mma.sync fp16 m16n8k16.
// R9 CHAMPION — byte-identical; measured at ~100% of the classical-path HMMA
// dispatch floor (523 of 512 MACs/cyc/SM model), so it is frozen.
// 128 threads = 4 warps, warp tile 64x64. 296 CTAs (2/SM), even share of 66048
// tiles; position boundary -> RED flush. SMEM 64KB: A0 A1 W0 W1.
// ================================================================================
__global__ void __launch_bounds__(128, 2) mma_main() {
    extern __shared__ __align__(1024) char smem[];
    const uint32_t sbase = smem_u32(smem);
    const uint32_t sA[2] = { sbase,         sbase + 16384 };
    const uint32_t sW[2] = { sbase + 32768, sbase + 49152 };

    const int tid = threadIdx.x;
    const int L   = tid & 31;
    const int wid = tid >> 5;
    const int wm  = wid & 1;    // M half (64 rows)
    const int wn  = wid >> 1;   // N half (64 cols)

    // ldsm lane constants
    const int lsw  = L & 7;
    const int rowA = (L & 7) + ((L >> 3) & 1) * 8;
    const int hiA  = (L >> 4) & 1;
    const int rowB = (L & 7) + ((L >> 4) & 1) * 8;
    const int hiB  = (L >> 3) & 1;
    uint32_t swzA[4], swzB[4], aoff[4], boff[4];
#pragma unroll
    for (int q = 0; q < 4; q++) {
        swzA[q] = ((uint32_t)((2 * q + hiA) ^ lsw)) << 4;
        swzB[q] = ((uint32_t)((2 * q + hiB) ^ lsw)) << 4;
    }
#pragma unroll
    for (int f = 0; f < 4; f++) {
        aoff[f] = (uint32_t)(wm * 64 + f * 16 + rowA) * 128;
        boff[f] = (uint32_t)(wn * 64 + f * 16 + rowB) * 128;
    }

    const uint32_t genO = (uint32_t)tid * 128;
    const uint32_t gsw  = (uint32_t)(tid & 7);
    const uint32_t wO   = (uint32_t)tid * 128;

    float acc[4][8][4];
    uint32_t bregh[32];   // b[myrow][jc*64 .. +63] as fp16x2

    // even share of global tiles
    const int start = (int)(((long long)blockIdx.x * TOTT) / NCTA);
    const int end   = (int)(((long long)(blockIdx.x + 1) * TOTT) / NCTA);

#define LDB(jc_) { _Pragma("unroll") \
    for (int e = 0; e < 32; e++) { \
        float x0 = __ldg(bTb + (size_t)((jc_) * 64 + 2 * e)     * B_SZ); \
        float x1 = __ldg(bTb + (size_t)((jc_) * 64 + 2 * e + 1) * B_SZ); \
        bregh[e] = pkh2(x0, x1); } }

#define GENA(buf_, av_) { const float av__ = (av_); _Pragma("unroll") \
    for (int w = 0; w < 8; w++) { \
        uint32_t p[4]; \
        _Pragma("unroll") \
        for (int u = 0; u < 4; u++) { \
            float2 bf = __half22float2(*(__half2*)&bregh[w * 4 + u]); \
            p[u] = pkh2(av__ * bf.x, av__ * bf.y); } \
        asm volatile("st.shared.v4.b32 [%0], {%1,%2,%3,%4};" \
            :: "r"(sA[buf_] + genO + (((uint32_t)w ^ gsw) << 4)), \
               "r"(p[0]), "r"(p[1]), "r"(p[2]), "r"(p[3]) : "memory"); } }

#define GENE(buf_, et_) { _Pragma("unroll") \
    for (int w = 0; w < 8; w++) { \
        float v[8]; \
        _Pragma("unroll") \
        for (int r = 0; r < 8; r++) { \
            const int ke = (et_) * 64 + w * 8 + r; \
            float x; \
            if (ke < 256)       x = __ldg(aTb + (size_t)ke * B_SZ); \
            else if (ke == 256) x = 1.0f; \
            else                x = __ldg(bTb + (size_t)(ke - 257) * B_SZ); \
            v[r] = x; } \
        uint32_t p0 = pkh2(v[0], v[1]), p1 = pkh2(v[2], v[3]); \
        uint32_t p2 = pkh2(v[4], v[5]), p3 = pkh2(v[6], v[7]); \
        asm volatile("st.shared.v4.b32 [%0], {%1,%2,%3,%4};" \
            :: "r"(sA[buf_] + genO + (((uint32_t)w ^ gsw) << 4)), \
               "r"(p0), "r"(p1), "r"(p2), "r"(p3) : "memory"); } }

#define CPW(buf_, i_, jc_) { const __half* src__ = wRow + (size_t)(i_) * 256 + (jc_) * 64; \
    _Pragma("unroll") \
    for (int w = 0; w < 8; w++) \
        cp16(sW[buf_] + wO + (((uint32_t)w ^ gsw) << 4), src__ + w * 8); \
    asm volatile("cp.async.commit_group;"); }

#define CPWE(buf_, et_) { const __half* src__ = eRow + (et_) * 64; \
    _Pragma("unroll") \
    for (int w = 0; w < 8; w++) \
        cp16(sW[buf_] + wO + (((uint32_t)w ^ gsw) << 4), src__ + w * 8); \
    asm volatile("cp.async.commit_group;"); }

    int t = start;
    while (t < end) {
        const int pos = t / TPP;
        const int pend = (pos + 1) * TPP < end ? (pos + 1) * TPP : end;
        const int ls = t - pos * TPP;
        const int le = pend - pos * TPP;
        const int m0 = (pos >> 1) * 128;
        const int n0 = (pos & 1) * 128;

        const float* aTb = g_aT + m0 + tid;
        const float* bTb = g_bT + m0 + tid;
        const __half* wRow = g_W1t + (size_t)(n0 + tid) * KP2H;
        const __half* eRow = g_W1e + (size_t)(n0 + tid) * 512;

#pragma unroll
        for (int mf = 0; mf < 4; mf++)
#pragma unroll
            for (int nf = 0; nf < 8; nf++)
#pragma unroll
                for (int e = 0; e < 4; e++) acc[mf][nf][e] = 0.0f;

        __syncthreads();  // protect buffers from lagging warps of prev segment

        // prologue: tile ls into buffer 0
        int jc_cur = -1;
        float av = 0.0f;
        if (ls < 1024) {
            jc_cur = ls >> 8;
            LDB(jc_cur);
            av = __ldg(aTb + (size_t)(ls & 255) * B_SZ);
            GENA(0, av);
            CPW(0, ls & 255, jc_cur);
        } else {
            GENE(0, ls - 1024);
            CPWE(0, ls - 1024);
        }
        float av_pf = 0.0f;
        if (ls + 1 < le && ls + 1 < 1024)
            av_pf = __ldg(aTb + (size_t)((ls + 1) & 255) * B_SZ);

        int buf = 0;
        for (int T = ls; T < le; T++) {
            asm volatile("cp.async.wait_group 0;");
            __syncthreads();

            if (T + 1 < le) {
                const int nt = T + 1;
                if (nt >= 1024) {
                    GENE(buf ^ 1, nt - 1024);
                    CPWE(buf ^ 1, nt - 1024);
                } else {
                    if ((nt >> 8) != jc_cur) { jc_cur = nt >> 8; LDB(jc_cur); }
                    GENA(buf ^ 1, av_pf);
                    CPW(buf ^ 1, nt & 255, jc_cur);
                    if (T + 2 < le && T + 2 < 1024)
                        av_pf = __ldg(aTb + (size_t)((T + 2) & 255) * B_SZ);
                }
            }

            // MMA on current buffer: 4 k-steps of 16
#pragma unroll
            for (int q = 0; q < 4; q++) {
                uint32_t afr[4][4], bfr[4][4];
#pragma unroll
                for (int mf = 0; mf < 4; mf++)
                    ldsm4(sA[buf] + aoff[mf] + swzA[q], afr[mf]);
#pragma unroll
                for (int n2 = 0; n2 < 4; n2++)
                    ldsm4(sW[buf] + boff[n2] + swzB[q], bfr[n2]);
#pragma unroll
                for (int mf = 0; mf < 4; mf++)
#pragma unroll
                    for (int nf = 0; nf < 8; nf++)
                        mma_f16(acc[mf][nf], afr[mf], &bfr[nf >> 1][(nf & 1) * 2]);
            }
            buf ^= 1;
        }

        // flush this position's contribution (RED)
#pragma unroll
        for (int mf = 0; mf < 4; mf++) {
            const int gm = m0 + wm * 64 + mf * 16 + (L >> 2);
#pragma unroll
            for (int nf = 0; nf < 8; nf++) {
                const int gn = n0 + wn * 64 + nf * 8 + 2 * (L & 3);
                float* p0 = g_acc + (size_t)gm * NN + gn;
                float* p1 = g_acc + (size_t)(gm + 8) * NN + gn;
                atomicAdd(p0,     acc[mf][nf][0]);
                atomicAdd(p0 + 1, acc[mf][nf][1]);
                atomicAdd(p1,     acc[mf][nf][2]);
                atomicAdd(p1 + 1, acc[mf][nf][3]);
            }
        }

        t = pend;
    }
}

// ================================================================================
// Reduce: g_acc + leftover edge column (ke=512 -> i=256,j=255) + b1 + relu -> h,
// then layer2 FFMA2 + b2 + relu. 256 CTAs x 16 rows (2x parallelism vs before).
// ================================================================================
__global__ void __launch_bounds__(256) reduce_l2(
    const float* __restrict__ W1, const float* __restrict__ b1,
    const float* __restrict__ W2, const float* __restrict__ b2,
    float* __restrict__ out) {
    __shared__ float h_t[256 * 18];  // h transposed: h_t[k][m], stride 18 (8B-aligned pairs)
    const int m0 = blockIdx.x * 16;
    const int n  = threadIdx.x;

    const float bb1 = __ldg(b1 + n);
    // leftover edge term: fusion[m, 256*257+255] = b[m,255]; weight row 66047
    const float wlast = __ldg(W1 + (size_t)66047 * NN + n);
#pragma unroll
    for (int q = 0; q < 16; q++) {
        const float blast = __ldg(g_bT + (size_t)255 * B_SZ + m0 + q);
        float sum = fmaf(blast, wlast, bb1) + g_acc[(size_t)(m0 + q) * NN + n];
        h_t[n * 18 + q] = fmaxf(sum, 0.0f);
    }
    __syncthreads();

    unsigned long long acc[8];
#pragma unroll
    for (int mp = 0; mp < 8; mp++) acc[mp] = 0ull;

#pragma unroll 4
    for (int k = 0; k < NN; k++) {
        const unsigned long long wp = pk1(__ldg(W2 + (size_t)k * NN + n));
        const float* hk = &h_t[k * 18];
#pragma unroll
        for (int mp = 0; mp < 8; mp++) {
            unsigned long long hv = *(const unsigned long long*)(hk + 2 * mp);
            acc[mp] = ffma2(hv, wp, acc[mp]);
        }
    }

    const float bb2 = __ldg(b2 + n);
#pragma unroll
    for (int mp = 0; mp < 8; mp++) {
        float x, y;
        upk(acc[mp], x, y);
        out[(size_t)(m0 + 2 * mp) * NN + n]     = fmaxf(x + bb2, 0.0f);
        out[(size_t)(m0 + 2 * mp + 1) * NN + n] = fmaxf(y + bb2, 0.0f);
    }
}

// ================================================================================
extern "C" void kernel_launch(void* const* d_in, const int* in_sizes, int n_in,
                              void* d_out, int out_size) {
    const float* inp1 = (const float*)d_in[0];
    const float* inp2 = (const float*)d_in[1];
    const float* W1   = (const float*)d_in[2];
    const float* b1   = (const float*)d_in[3];
    const float* W2   = (const float*)d_in[4];
    const float* b2   = (const float*)d_in[5];
    float* out = (float*)d_out;

    cudaFuncSetAttribute(mma_main, cudaFuncAttributeMaxDynamicSharedMemorySize, 65536);

    prep_inputs<<<dim3(128, 8, 2), 256>>>(inp1, inp2);   // also zeroes g_acc
    prep_w1<<<dim3(256, 4, 8), 256>>>(W1);
    prep_w1e<<<dim3(16, 8), 256>>>(W1);
    mma_main<<<NCTA, 128, 65536>>>();
    reduce_l2<<<B_SZ / 16, 256>>>(W1, b1, W2, b2, out);
}

// round 16
// speedup vs baseline: 1.3060x; 1.0553x over previous
#include <cuda_runtime.h>
#include <cuda_fp16.h>
#include <cstdint>

#define B_SZ   4096
#define NN     256
#define NA     257
#define KP2H   65536        // W1t row length in halves: 256 i-blocks * 256
#define NPOS   64           // 32 M-blocks x 2 N-blocks
#define TPP    1032         // K-tiles per position: 1024 regular + 8 edge
#define TOTT   (NPOS * TPP) // 66048 total tiles
#define NCTA   296          // 2 per SM, single wave

// ---------------- device-global scratch (no allocation allowed) ----------------
__device__ __align__(256) __half g_W1t[(size_t)NN * KP2H];          // 33.5 MB
__device__ __align__(256) __half g_W1e[(size_t)NN * 512];           // 256 KB edge weights
__device__ __align__(256) float  g_aT [(size_t)256 * B_SZ];         // 4 MB
__device__ __align__(256) float  g_bT [(size_t)256 * B_SZ];         // 4 MB
__device__ __align__(256) __half g_bh [(size_t)B_SZ * 256];         // 2 MB (b m-major fp16)
__device__ __align__(256) float  g_acc[(size_t)B_SZ * NN];          // 4 MB accumulator

// ---------------- helpers ----------------
static __device__ __forceinline__ uint32_t smem_u32(const void* p) {
    uint32_t a;
    asm("{ .reg .u64 t; cvta.to.shared.u64 t, %1; cvt.u32.u64 %0, t; }" : "=r"(a) : "l"(p));
    return a;
}
static __device__ __forceinline__ void cp16(uint32_t s, const void* g) {
    asm volatile("cp.async.cg.shared.global [%0], [%1], 16;" :: "r"(s), "l"(g));
}
// pack (lo,hi) fp32 -> f16x2 (single final rounding, RN)
static __device__ __forceinline__ uint32_t pkh2(float lo, float hi) {
    uint32_t r;
    asm("cvt.rn.f16x2.f32 %0, %1, %2;" : "=r"(r) : "f"(hi), "f"(lo));
    return r;
}
static __device__ __forceinline__ uint32_t hmul2(uint32_t a, uint32_t b) {
    uint32_t r;
    asm("mul.rn.f16x2 %0, %1, %2;" : "=r"(r) : "r"(a), "r"(b));
    return r;
}
static __device__ __forceinline__ unsigned long long pk1(float x) {
    unsigned long long r;
    asm("mov.b64 %0, {%1, %1};" : "=l"(r) : "f"(x));
    return r;
}
static __device__ __forceinline__ unsigned long long ffma2(
    unsigned long long a, unsigned long long b, unsigned long long c) {
    unsigned long long d;
    asm("fma.rn.f32x2 %0, %1, %2, %3;" : "=l"(d) : "l"(a), "l"(b), "l"(c));
    return d;
}
static __device__ __forceinline__ void upk(unsigned long long v, float& x, float& y) {
    asm("mov.b64 {%0, %1}, %2;" : "=f"(x), "=f"(y) : "l"(v));
}
static __device__ __forceinline__ void ldsm4(uint32_t addr, uint32_t r[4]) {
    asm volatile("ldmatrix.sync.aligned.m8n8.x4.shared.b16 {%0,%1,%2,%3}, [%4];"
                 : "=r"(r[0]), "=r"(r[1]), "=r"(r[2]), "=r"(r[3]) : "r"(addr));
}
static __device__ __forceinline__ void mma_f16(
    float d[4], const uint32_t a[4], const uint32_t b[2]) {
    asm volatile(
        "mma.sync.aligned.m16n8k16.row.col.f32.f16.f16.f32 "
        "{%0,%1,%2,%3}, {%4,%5,%6,%7}, {%8,%9}, {%0,%1,%2,%3};"
        : "+f"(d[0]), "+f"(d[1]), "+f"(d[2]), "+f"(d[3])
        : "r"(a[0]), "r"(a[1]), "r"(a[2]), "r"(a[3]), "r"(b[0]), "r"(b[1]));
}

// ================================================================================
// Pre-pass 1: transpose inp1 / inp2 -> g_aT / g_bT (fp32) + zero g_acc (merged)
// ================================================================================
__global__ void __launch_bounds__(256) prep_inputs(
    const float* __restrict__ in1, const float* __restrict__ in2) {
    __shared__ float tile[32 * 33];
    const float* src = blockIdx.z ? in2 : in1;
    float* dst = blockIdx.z ? g_bT : g_aT;
    const int m0 = blockIdx.x * 32, c0 = blockIdx.y * 32;
    const int c = threadIdx.x & 31, r0 = threadIdx.x >> 5;

    // merged accumulator zeroing: 2048 blocks x 256 thr x 1 float2 = 1M floats
    {
        const int bid = (blockIdx.z * gridDim.y + blockIdx.y) * gridDim.x + blockIdx.x;
        const int idx = bid * 256 + threadIdx.x;
        ((float2*)g_acc)[idx] = make_float2(0.f, 0.f);
    }

#pragma unroll
    for (int q = 0; q < 4; q++) {
        int r = r0 + q * 8;
        tile[c * 33 + r] = src[(size_t)(m0 + r) * 256 + c0 + c];
    }
    __syncthreads();
#pragma unroll
    for (int q = 0; q < 4; q++) {
        int rr = r0 + q * 8;
        dst[(size_t)(c0 + rr) * B_SZ + m0 + c] = tile[rr * 33 + c];
    }
}

// ================================================================================
// Pre-pass 1b: g_bh[m][j] = fp16(inp2[m][j]), m-major, coalesced u32 stores
// ================================================================================
__global__ void __launch_bounds__(128) prep_bh(const float* __restrict__ in2) {
    const int m = blockIdx.x;
    const int t = threadIdx.x;
    const float lo = in2[(size_t)m * 256 + 2 * t];
    const float hi = in2[(size_t)m * 256 + 2 * t + 1];
    ((uint32_t*)g_bh)[(size_t)m * 128 + t] = pkh2(lo, hi);
}

// ================================================================================
// Pre-pass 2: W1t[n][i*256 + j] = fp16(W1[i*257+j][n]),  i<256, j<256
// Retiled 64j x 32n so fp16 writes are full 128B/warp. grid (256, 4, 8).
// ================================================================================
__global__ void __launch_bounds__(256) prep_w1(const float* __restrict__ W1) {
    __shared__ float tile[64 * 33];   // [j][n], padded
    const int i  = blockIdx.x;
    const int j0 = blockIdx.y * 64;
    const int n0 = blockIdx.z * 32;
    const int tid = threadIdx.x;
    const int c = tid & 31, r0 = tid >> 5;
#pragma unroll
    for (int q = 0; q < 8; q++) {
        int j = r0 + q * 8;
        tile[j * 33 + c] = W1[((size_t)i * NA + j0 + j) * NN + n0 + c];
    }
    __syncthreads();
    uint32_t* dst32 = (uint32_t*)g_W1t;
#pragma unroll
    for (int q = 0; q < 4; q++) {
        int e = tid + q * 256;
        int n  = e >> 5;          // 0..31
        int jj = e & 31;          // u32 (2 halves) within the 64-j chunk
        float lo = tile[(2 * jj)     * 33 + n];
        float hi = tile[(2 * jj + 1) * 33 + n];
        dst32[(((size_t)(n0 + n) * KP2H + (size_t)i * 256 + j0) >> 1) + jj] = pkh2(lo, hi);
    }
}

// ================================================================================
// Pre-pass 3: edge weights. ke<257 -> W1 row ke*257+256 ; 257<=ke<512 -> row
// 65792+(ke-257).  g_W1e[n][ke] = fp16(W1[row(ke)][n]).
// ================================================================================
__global__ void __launch_bounds__(256) prep_w1e(const float* __restrict__ W1) {
    __shared__ float tile[32 * 33];
    const int k0 = blockIdx.x * 32, n0 = blockIdx.y * 32;
    const int c = threadIdx.x & 31, r0 = threadIdx.x >> 5;
#pragma unroll
    for (int q = 0; q < 4; q++) {
        int kr = r0 + q * 8;
        int ke = k0 + kr;
        size_t row = (ke < 257) ? ((size_t)ke * NA + 256)
                                : ((size_t)256 * NA + (ke - 257));
        tile[c * 33 + kr] = W1[row * NN + n0 + c];
    }
    __syncthreads();
#pragma unroll
    for (int q = 0; q < 4; q++) {
        int nr = r0 + q * 8;
        g_W1e[(size_t)(n0 + nr) * 512 + k0 + c] = __float2half_rn(tile[nr * 33 + c]);
    }
}

// ================================================================================
// Main: persistent balanced split-K implicit GEMM, mma.sync fp16 m16n8k16.
// R9 champion skeleton (128 thr = 4 warps, warp tile 64x64, 296 CTAs = 2/SM),
// DESPILLED: bregh[32] registers replaced by a per-jc SMEM b-stage (sBH, 16KB)
// filled by per-thread cp.async from precomputed g_bh once per 256 tiles.
// Each thread reads back only its OWN staged row -> wait_group 0 suffices, no
// extra barrier. GENA = 8 LDS.128 + 32 HMUL2 + 8 STS.128 (was ~160 instr).
// SMEM 80KB: A0 A1 W0 W1 sBH.
// ================================================================================
__global__ void __launch_bounds__(128, 2) mma_main() {
    extern __shared__ __align__(1024) char smem[];
    const uint32_t sbase = smem_u32(smem);
    const uint32_t sA[2] = { sbase,         sbase + 16384 };
    const uint32_t sW[2] = { sbase + 32768, sbase + 49152 };
    const uint32_t sBH   = sbase + 65536;

    const int tid = threadIdx.x;
    const int L   = tid & 31;
    const int wid = tid >> 5;
    const int wm  = wid & 1;    // M half (64 rows)
    const int wn  = wid >> 1;   // N half (64 cols)

    // ldsm lane constants
    const int lsw  = L & 7;
    const int rowA = (L & 7) + ((L >> 3) & 1) * 8;
    const int hiA  = (L >> 4) & 1;
    const int rowB = (L & 7) + ((L >> 4) & 1) * 8;
    const int hiB  = (L >> 3) & 1;
    uint32_t swzA[4], swzB[4], aoff[4], boff[4];
#pragma unroll
    for (int q = 0; q < 4; q++) {
        swzA[q] = ((uint32_t)((2 * q + hiA) ^ lsw)) << 4;
        swzB[q] = ((uint32_t)((2 * q + hiB) ^ lsw)) << 4;
    }
#pragma unroll
    for (int f = 0; f < 4; f++) {
        aoff[f] = (uint32_t)(wm * 64 + f * 16 + rowA) * 128;
        boff[f] = (uint32_t)(wn * 64 + f * 16 + rowB) * 128;
    }

    const uint32_t genO = (uint32_t)tid * 128;
    const uint32_t gsw  = (uint32_t)(tid & 7);
    const uint32_t wO   = (uint32_t)tid * 128;

    float acc[4][8][4];

    // even share of global tiles
    const int start = (int)(((long long)blockIdx.x * TOTT) / NCTA);
    const int end   = (int)(((long long)(blockIdx.x + 1) * TOTT) / NCTA);

// Stage this thread's b-row chunk for jc into sBH (8 cp.async + own commit+wait)
#define STAGEBH(jc_) { const char* bsrc__ = bhRow + (jc_) * 128; \
    _Pragma("unroll") \
    for (int w = 0; w < 8; w++) \
        cp16(sBH + genO + (((uint32_t)w ^ gsw) << 4), bsrc__ + w * 16); \
    asm volatile("cp.async.commit_group;"); \
    asm volatile("cp.async.wait_group 0;"); }

// A-gen: 8x (LDS.128 fp16 b-pairs + 4 HMUL2 + STS.128); av2 = (av,av) fp16x2
#define GENA(buf_, av_) { const uint32_t av2__ = pkh2(av_, av_); \
    _Pragma("unroll") \
    for (int w = 0; w < 8; w++) { \
        uint32_t b0__, b1__, b2__, b3__; \
        asm volatile("ld.shared.v4.b32 {%0,%1,%2,%3}, [%4];" \
            : "=r"(b0__), "=r"(b1__), "=r"(b2__), "=r"(b3__) \
            : "r"(sBH + genO + (((uint32_t)w ^ gsw) << 4))); \
        uint32_t p0__ = hmul2(b0__, av2__); \
        uint32_t p1__ = hmul2(b1__, av2__); \
        uint32_t p2__ = hmul2(b2__, av2__); \
        uint32_t p3__ = hmul2(b3__, av2__); \
        asm volatile("st.shared.v4.b32 [%0], {%1,%2,%3,%4};" \
            :: "r"(sA[buf_] + genO + (((uint32_t)w ^ gsw) << 4)), \
               "r"(p0__), "r"(p1__), "r"(p2__), "r"(p3__) : "memory"); } }

#define GENE(buf_, et_) { _Pragma("unroll") \
    for (int w = 0; w < 8; w++) { \
        float v[8]; \
        _Pragma("unroll") \
        for (int r = 0; r < 8; r++) { \
            const int ke = (et_) * 64 + w * 8 + r; \
            float x; \
            if (ke < 256)       x = __ldg(aTb + (size_t)ke * B_SZ); \
            else if (ke == 256) x = 1.0f; \
            else                x = __ldg(bTb + (size_t)(ke - 257) * B_SZ); \
            v[r] = x; } \
        uint32_t p0 = pkh2(v[0], v[1]), p1 = pkh2(v[2], v[3]); \
        uint32_t p2 = pkh2(v[4], v[5]), p3 = pkh2(v[6], v[7]); \
        asm volatile("st.shared.v4.b32 [%0], {%1,%2,%3,%4};" \
            :: "r"(sA[buf_] + genO + (((uint32_t)w ^ gsw) << 4)), \
               "r"(p0), "r"(p1), "r"(p2), "r"(p3) : "memory"); } }

#define CPW(buf_, i_, jc_) { const __half* src__ = wRow + (size_t)(i_) * 256 + (jc_) * 64; \
    _Pragma("unroll") \
    for (int w = 0; w < 8; w++) \
        cp16(sW[buf_] + wO + (((uint32_t)w ^ gsw) << 4), src__ + w * 8); \
    asm volatile("cp.async.commit_group;"); }

#define CPWE(buf_, et_) { const __half* src__ = eRow + (et_) * 64; \
    _Pragma("unroll") \
    for (int w = 0; w < 8; w++) \
        cp16(sW[buf_] + wO + (((uint32_t)w ^ gsw) << 4), src__ + w * 8); \
    asm volatile("cp.async.commit_group;"); }

    int t = start;
    while (t < end) {
        const int pos = t / TPP;
        const int pend = (pos + 1) * TPP < end ? (pos + 1) * TPP : end;
        const int ls = t - pos * TPP;
        const int le = pend - pos * TPP;
        const int m0 = (pos >> 1) * 128;
        const int n0 = (pos & 1) * 128;

        const float* aTb = g_aT + m0 + tid;
        const float* bTb = g_bT + m0 + tid;
        const char*  bhRow = (const char*)g_bh + (size_t)(m0 + tid) * 512;
        const __half* wRow = g_W1t + (size_t)(n0 + tid) * KP2H;
        const __half* eRow = g_W1e + (size_t)(n0 + tid) * 512;

#pragma unroll
        for (int mf = 0; mf < 4; mf++)
#pragma unroll
            for (int nf = 0; nf < 8; nf++)
#pragma unroll
                for (int e = 0; e < 4; e++) acc[mf][nf][e] = 0.0f;

        __syncthreads();  // protect buffers from lagging warps of prev segment

        // prologue: tile ls into buffer 0
        int jc_cur = -1;
        float av = 0.0f;
        if (ls < 1024) {
            jc_cur = ls >> 8;
            STAGEBH(jc_cur);
            av = __ldg(aTb + (size_t)(ls & 255) * B_SZ);
            GENA(0, av);
            CPW(0, ls & 255, jc_cur);
        } else {
            GENE(0, ls - 1024);
            CPWE(0, ls - 1024);
        }
        float av_pf = 0.0f;
        if (ls + 1 < le && ls + 1 < 1024)
            av_pf = __ldg(aTb + (size_t)((ls + 1) & 255) * B_SZ);

        int buf = 0;
        for (int T = ls; T < le; T++) {
            asm volatile("cp.async.wait_group 0;");
            __syncthreads();

            if (T + 1 < le) {
                const int nt = T + 1;
                if (nt >= 1024) {
                    GENE(buf ^ 1, nt - 1024);
                    CPWE(buf ^ 1, nt - 1024);
                } else {
                    if ((nt >> 8) != jc_cur) {
                        jc_cur = nt >> 8;
                        STAGEBH(jc_cur);   // own rows only; wait_group 0 inside
                    }
                    GENA(buf ^ 1, av_pf);
                    CPW(buf ^ 1, nt & 255, jc_cur);
                    if (T + 2 < le && T + 2 < 1024)
                        av_pf = __ldg(aTb + (size_t)((T + 2) & 255) * B_SZ);
                }
            }

            // MMA on current buffer: 4 k-steps of 16
#pragma unroll
            for (int q = 0; q < 4; q++) {
                uint32_t afr[4][4], bfr[4][4];
#pragma unroll
                for (int mf = 0; mf < 4; mf++)
                    ldsm4(sA[buf] + aoff[mf] + swzA[q], afr[mf]);
#pragma unroll
                for (int n2 = 0; n2 < 4; n2++)
                    ldsm4(sW[buf] + boff[n2] + swzB[q], bfr[n2]);
#pragma unroll
                for (int mf = 0; mf < 4; mf++)
#pragma unroll
                    for (int nf = 0; nf < 8; nf++)
                        mma_f16(acc[mf][nf], afr[mf], &bfr[nf >> 1][(nf & 1) * 2]);
            }
            buf ^= 1;
        }

        // flush this position's contribution (RED)
#pragma unroll
        for (int mf = 0; mf < 4; mf++) {
            const int gm = m0 + wm * 64 + mf * 16 + (L >> 2);
#pragma unroll
            for (int nf = 0; nf < 8; nf++) {
                const int gn = n0 + wn * 64 + nf * 8 + 2 * (L & 3);
                float* p0 = g_acc + (size_t)gm * NN + gn;
                float* p1 = g_acc + (size_t)(gm + 8) * NN + gn;
                atomicAdd(p0,     acc[mf][nf][0]);
                atomicAdd(p0 + 1, acc[mf][nf][1]);
                atomicAdd(p1,     acc[mf][nf][2]);
                atomicAdd(p1 + 1, acc[mf][nf][3]);
            }
        }

        t = pend;
    }
}

// ================================================================================
// Reduce: g_acc + leftover edge column (ke=512 -> i=256,j=255) + b1 + relu -> h,
// then layer2 FFMA2 + b2 + relu. 256 CTAs x 16 rows.
// ================================================================================
__global__ void __launch_bounds__(256) reduce_l2(
    const float* __restrict__ W1, const float* __restrict__ b1,
    const float* __restrict__ W2, const float* __restrict__ b2,
    float* __restrict__ out) {
    __shared__ float h_t[256 * 18];  // h transposed: h_t[k][m], stride 18
    const int m0 = blockIdx.x * 16;
    const int n  = threadIdx.x;

    const float bb1 = __ldg(b1 + n);
    // leftover edge term: fusion[m, 256*257+255] = b[m,255]; weight row 66047
    const float wlast = __ldg(W1 + (size_t)66047 * NN + n);
#pragma unroll
    for (int q = 0; q < 16; q++) {
        const float blast = __ldg(g_bT + (size_t)255 * B_SZ + m0 + q);
        float sum = fmaf(blast, wlast, bb1) + g_acc[(size_t)(m0 + q) * NN + n];
        h_t[n * 18 + q] = fmaxf(sum, 0.0f);
    }
    __syncthreads();

    unsigned long long acc[8];
#pragma unroll
    for (int mp = 0; mp < 8; mp++) acc[mp] = 0ull;

#pragma unroll 4
    for (int k = 0; k < NN; k++) {
        const unsigned long long wp = pk1(__ldg(W2 + (size_t)k * NN + n));
        const float* hk = &h_t[k * 18];
#pragma unroll
        for (int mp = 0; mp < 8; mp++) {
            unsigned long long hv = *(const unsigned long long*)(hk + 2 * mp);
            acc[mp] = ffma2(hv, wp, acc[mp]);
        }
    }

    const float bb2 = __ldg(b2 + n);
#pragma unroll
    for (int mp = 0; mp < 8; mp++) {
        float x, y;
        upk(acc[mp], x, y);
        out[(size_t)(m0 + 2 * mp) * NN + n]     = fmaxf(x + bb2, 0.0f);
        out[(size_t)(m0 + 2 * mp + 1) * NN + n] = fmaxf(y + bb2, 0.0f);
    }
}

// ================================================================================
extern "C" void kernel_launch(void* const* d_in, const int* in_sizes, int n_in,
                              void* d_out, int out_size) {
    const float* inp1 = (const float*)d_in[0];
    const float* inp2 = (const float*)d_in[1];
    const float* W1   = (const float*)d_in[2];
    const float* b1   = (const float*)d_in[3];
    const float* W2   = (const float*)d_in[4];
    const float* b2   = (const float*)d_in[5];
    float* out = (float*)d_out;

    cudaFuncSetAttribute(mma_main, cudaFuncAttributeMaxDynamicSharedMemorySize, 81920);

    prep_inputs<<<dim3(128, 8, 2), 256>>>(inp1, inp2);   // also zeroes g_acc
    prep_bh<<<B_SZ, 128>>>(inp2);
    prep_w1<<<dim3(256, 4, 8), 256>>>(W1);
    prep_w1e<<<dim3(16, 8), 256>>>(W1);
    mma_main<<<NCTA, 128, 81920>>>();
    reduce_l2<<<B_SZ / 16, 256>>>(W1, b1, W2, b2, out);
}

// round 17
// speedup vs baseline: 1.6618x; 1.2725x over previous
#include <cuda_runtime.h>
#include <cuda_fp16.h>
#include <cstdint>

#define B_SZ   4096
#define NN     256
#define NA     257
#define KP2H   65536        // W1t row length in halves: 256 i-blocks * 256
#define NPOS   64           // 32 M-blocks x 2 N-blocks
#define TPP    1032         // K-tiles per position: 1024 regular + 8 edge
#define TOTT   (NPOS * TPP) // 66048 total tiles
#define NCTA   296          // 2 per SM, single wave

// ---------------- device-global scratch (no allocation allowed) ----------------
__device__ __align__(256) __half g_W1t[(size_t)NN * KP2H];          // 33.5 MB
__device__ __align__(256) __half g_W1e[(size_t)NN * 512];           // 256 KB edge weights
__device__ __align__(256) float  g_aT [(size_t)256 * B_SZ];         // 4 MB
__device__ __align__(256) float  g_bT [(size_t)256 * B_SZ];         // 4 MB
__device__ __align__(256) __half g_bh [(size_t)B_SZ * 256];         // 2 MB (b m-major fp16)
__device__ __align__(256) float  g_acc[(size_t)B_SZ * NN];          // 4 MB accumulator

// ---------------- helpers ----------------
static __device__ __forceinline__ uint32_t smem_u32(const void* p) {
    uint32_t a;
    asm("{ .reg .u64 t; cvta.to.shared.u64 t, %1; cvt.u32.u64 %0, t; }" : "=r"(a) : "l"(p));
    return a;
}
static __device__ __forceinline__ void cp16(uint32_t s, const void* g) {
    asm volatile("cp.async.cg.shared.global [%0], [%1], 16;" :: "r"(s), "l"(g));
}
// pack (lo,hi) fp32 -> f16x2 (single final rounding, RN)
static __device__ __forceinline__ uint32_t pkh2(float lo, float hi) {
    uint32_t r;
    asm("cvt.rn.f16x2.f32 %0, %1, %2;" : "=r"(r) : "f"(hi), "f"(lo));
    return r;
}
static __device__ __forceinline__ uint32_t hmul2(uint32_t a, uint32_t b) {
    uint32_t r;
    asm("mul.rn.f16x2 %0, %1, %2;" : "=r"(r) : "r"(a), "r"(b));
    return r;
}
static __device__ __forceinline__ unsigned long long pk1(float x) {
    unsigned long long r;
    asm("mov.b64 %0, {%1, %1};" : "=l"(r) : "f"(x));
    return r;
}
static __device__ __forceinline__ unsigned long long ffma2(
    unsigned long long a, unsigned long long b, unsigned long long c) {
    unsigned long long d;
    asm("fma.rn.f32x2 %0, %1, %2, %3;" : "=l"(d) : "l"(a), "l"(b), "l"(c));
    return d;
}
static __device__ __forceinline__ void upk(unsigned long long v, float& x, float& y) {
    asm("mov.b64 {%0, %1}, %2;" : "=f"(x), "=f"(y) : "l"(v));
}
static __device__ __forceinline__ void ldsm4(uint32_t addr, uint32_t r[4]) {
    asm volatile("ldmatrix.sync.aligned.m8n8.x4.shared.b16 {%0,%1,%2,%3}, [%4];"
                 : "=r"(r[0]), "=r"(r[1]), "=r"(r[2]), "=r"(r[3]) : "r"(addr));
}
static __device__ __forceinline__ void mma_f16(
    float d[4], const uint32_t a[4], const uint32_t b[2]) {
    asm volatile(
        "mma.sync.aligned.m16n8k16.row.col.f32.f16.f16.f32 "
        "{%0,%1,%2,%3}, {%4,%5,%6,%7}, {%8,%9}, {%0,%1,%2,%3};"
        : "+f"(d[0]), "+f"(d[1]), "+f"(d[2]), "+f"(d[3])
        : "r"(a[0]), "r"(a[1]), "r"(a[2]), "r"(a[3]), "r"(b[0]), "r"(b[1]));
}

// ================================================================================
// Pre-pass 1: transpose inp1 / inp2 -> g_aT / g_bT (fp32) + zero g_acc (merged)
// ================================================================================
__global__ void __launch_bounds__(256) prep_inputs(
    const float* __restrict__ in1, const float* __restrict__ in2) {
    __shared__ float tile[32 * 33];
    const float* src = blockIdx.z ? in2 : in1;
    float* dst = blockIdx.z ? g_bT : g_aT;
    const int m0 = blockIdx.x * 32, c0 = blockIdx.y * 32;
    const int c = threadIdx.x & 31, r0 = threadIdx.x >> 5;

    // merged accumulator zeroing: 2048 blocks x 256 thr x 1 float2 = 1M floats
    {
        const int bid = (blockIdx.z * gridDim.y + blockIdx.y) * gridDim.x + blockIdx.x;
        const int idx = bid * 256 + threadIdx.x;
        ((float2*)g_acc)[idx] = make_float2(0.f, 0.f);
    }

#pragma unroll
    for (int q = 0; q < 4; q++) {
        int r = r0 + q * 8;
        tile[c * 33 + r] = src[(size_t)(m0 + r) * 256 + c0 + c];
    }
    __syncthreads();
#pragma unroll
    for (int q = 0; q < 4; q++) {
        int rr = r0 + q * 8;
        dst[(size_t)(c0 + rr) * B_SZ + m0 + c] = tile[rr * 33 + c];
    }
}

// ================================================================================
// Pre-pass 1b: g_bh[m][j] = fp16(inp2[m][j]), m-major, coalesced u32 stores
// ================================================================================
__global__ void __launch_bounds__(128) prep_bh(const float* __restrict__ in2) {
    const int m = blockIdx.x;
    const int t = threadIdx.x;
    const float lo = in2[(size_t)m * 256 + 2 * t];
    const float hi = in2[(size_t)m * 256 + 2 * t + 1];
    ((uint32_t*)g_bh)[(size_t)m * 128 + t] = pkh2(lo, hi);
}

// ================================================================================
// Pre-pass 2: W1t[n][i*256 + j] = fp16(W1[i*257+j][n]),  i<256, j<256
// Retiled 64j x 32n so fp16 writes are full 128B/warp. grid (256, 4, 8).
// ================================================================================
__global__ void __launch_bounds__(256) prep_w1(const float* __restrict__ W1) {
    __shared__ float tile[64 * 33];   // [j][n], padded
    const int i  = blockIdx.x;
    const int j0 = blockIdx.y * 64;
    const int n0 = blockIdx.z * 32;
    const int tid = threadIdx.x;
    const int c = tid & 31, r0 = tid >> 5;
#pragma unroll
    for (int q = 0; q < 8; q++) {
        int j = r0 + q * 8;
        tile[j * 33 + c] = W1[((size_t)i * NA + j0 + j) * NN + n0 + c];
    }
    __syncthreads();
    uint32_t* dst32 = (uint32_t*)g_W1t;
#pragma unroll
    for (int q = 0; q < 4; q++) {
        int e = tid + q * 256;
        int n  = e >> 5;          // 0..31
        int jj = e & 31;          // u32 (2 halves) within the 64-j chunk
        float lo = tile[(2 * jj)     * 33 + n];
        float hi = tile[(2 * jj + 1) * 33 + n];
        dst32[(((size_t)(n0 + n) * KP2H + (size_t)i * 256 + j0) >> 1) + jj] = pkh2(lo, hi);
    }
}

// ================================================================================
// Pre-pass 3: edge weights. ke<257 -> W1 row ke*257+256 ; 257<=ke<512 -> row
// 65792+(ke-257).  g_W1e[n][ke] = fp16(W1[row(ke)][n]).
// ================================================================================
__global__ void __launch_bounds__(256) prep_w1e(const float* __restrict__ W1) {
    __shared__ float tile[32 * 33];
    const int k0 = blockIdx.x * 32, n0 = blockIdx.y * 32;
    const int c = threadIdx.x & 31, r0 = threadIdx.x >> 5;
#pragma unroll
    for (int q = 0; q < 4; q++) {
        int kr = r0 + q * 8;
        int ke = k0 + kr;
        size_t row = (ke < 257) ? ((size_t)ke * NA + 256)
                                : ((size_t)256 * NA + (ke - 257));
        tile[c * 33 + kr] = W1[row * NN + n0 + c];
    }
    __syncthreads();
#pragma unroll
    for (int q = 0; q < 4; q++) {
        int nr = r0 + q * 8;
        g_W1e[(size_t)(n0 + nr) * 512 + k0 + c] = __float2half_rn(tile[nr * 33 + c]);
    }
}

// ================================================================================
// Main: persistent balanced split-K implicit GEMM, mma.sync fp16 m16n8k16.
// R15 champion + INSTRUCTION-LEVEL INTERLEAVE: the 16 HMMA groups of tile T
// each carry one slice of tile T+1's prep (even slots: LDS b + cp16 W; odd
// slots: HMUL2 x4 + STS A), so tensor/LSU/fma pipes run concurrently inside
// each warp's in-order stream instead of phase-serialized bursts.
// 128 thr = 4 warps, warp tile 64x64, 296 CTAs (2/SM). SMEM 80KB.
// ================================================================================
__global__ void __launch_bounds__(128, 2) mma_main() {
    extern __shared__ __align__(1024) char smem[];
    const uint32_t sbase = smem_u32(smem);
    const uint32_t sA[2] = { sbase,         sbase + 16384 };
    const uint32_t sW[2] = { sbase + 32768, sbase + 49152 };
    const uint32_t sBH   = sbase + 65536;

    const int tid = threadIdx.x;
    const int L   = tid & 31;
    const int wid = tid >> 5;
    const int wm  = wid & 1;    // M half (64 rows)
    const int wn  = wid >> 1;   // N half (64 cols)

    // ldsm lane constants
    const int lsw  = L & 7;
    const int rowA = (L & 7) + ((L >> 3) & 1) * 8;
    const int hiA  = (L >> 4) & 1;
    const int rowB = (L & 7) + ((L >> 4) & 1) * 8;
    const int hiB  = (L >> 3) & 1;
    uint32_t swzA[4], swzB[4], aoff[4], boff[4];
#pragma unroll
    for (int q = 0; q < 4; q++) {
        swzA[q] = ((uint32_t)((2 * q + hiA) ^ lsw)) << 4;
        swzB[q] = ((uint32_t)((2 * q + hiB) ^ lsw)) << 4;
    }
#pragma unroll
    for (int f = 0; f < 4; f++) {
        aoff[f] = (uint32_t)(wm * 64 + f * 16 + rowA) * 128;
        boff[f] = (uint32_t)(wn * 64 + f * 16 + rowB) * 128;
    }

    const uint32_t genO = (uint32_t)tid * 128;
    const uint32_t gsw  = (uint32_t)(tid & 7);
    const uint32_t wO   = (uint32_t)tid * 128;

    float acc[4][8][4];

    // even share of global tiles
    const int start = (int)(((long long)blockIdx.x * TOTT) / NCTA);
    const int end   = (int)(((long long)(blockIdx.x + 1) * TOTT) / NCTA);

// Stage this thread's b-row chunk for jc into sBH (8 cp.async + own commit+wait)
#define STAGEBH(jc_) { const char* bsrc__ = bhRow + (jc_) * 128; \
    _Pragma("unroll") \
    for (int w = 0; w < 8; w++) \
        cp16(sBH + genO + (((uint32_t)w ^ gsw) << 4), bsrc__ + w * 16); \
    asm volatile("cp.async.commit_group;"); \
    asm volatile("cp.async.wait_group 0;"); }

// Full A-gen (prologue / fallback): 8x (LDS.128 + 4 HMUL2 + STS.128)
#define GENA(buf_, av_) { const uint32_t av2__ = pkh2(av_, av_); \
    _Pragma("unroll") \
    for (int w = 0; w < 8; w++) { \
        uint32_t b0__, b1__, b2__, b3__; \
        asm volatile("ld.shared.v4.b32 {%0,%1,%2,%3}, [%4];" \
            : "=r"(b0__), "=r"(b1__), "=r"(b2__), "=r"(b3__) \
            : "r"(sBH + genO + (((uint32_t)w ^ gsw) << 4))); \
        uint32_t p0__ = hmul2(b0__, av2__); \
        uint32_t p1__ = hmul2(b1__, av2__); \
        uint32_t p2__ = hmul2(b2__, av2__); \
        uint32_t p3__ = hmul2(b3__, av2__); \
        asm volatile("st.shared.v4.b32 [%0], {%1,%2,%3,%4};" \
            :: "r"(sA[buf_] + genO + (((uint32_t)w ^ gsw) << 4)), \
               "r"(p0__), "r"(p1__), "r"(p2__), "r"(p3__) : "memory"); } }

#define GENE(buf_, et_) { _Pragma("unroll") \
    for (int w = 0; w < 8; w++) { \
        float v[8]; \
        _Pragma("unroll") \
        for (int r = 0; r < 8; r++) { \
            const int ke = (et_) * 64 + w * 8 + r; \
            float x; \
            if (ke < 256)       x = __ldg(aTb + (size_t)ke * B_SZ); \
            else if (ke == 256) x = 1.0f; \
            else                x = __ldg(bTb + (size_t)(ke - 257) * B_SZ); \
            v[r] = x; } \
        uint32_t p0 = pkh2(v[0], v[1]), p1 = pkh2(v[2], v[3]); \
        uint32_t p2 = pkh2(v[4], v[5]), p3 = pkh2(v[6], v[7]); \
        asm volatile("st.shared.v4.b32 [%0], {%1,%2,%3,%4};" \
            :: "r"(sA[buf_] + genO + (((uint32_t)w ^ gsw) << 4)), \
               "r"(p0), "r"(p1), "r"(p2), "r"(p3) : "memory"); } }

#define CPW(buf_, i_, jc_) { const __half* src__ = wRow + (size_t)(i_) * 256 + (jc_) * 64; \
    _Pragma("unroll") \
    for (int w = 0; w < 8; w++) \
        cp16(sW[buf_] + wO + (((uint32_t)w ^ gsw) << 4), src__ + w * 8); \
    asm volatile("cp.async.commit_group;"); }

#define CPWE(buf_, et_) { const __half* src__ = eRow + (et_) * 64; \
    _Pragma("unroll") \
    for (int w = 0; w < 8; w++) \
        cp16(sW[buf_] + wO + (((uint32_t)w ^ gsw) << 4), src__ + w * 8); \
    asm volatile("cp.async.commit_group;"); }

// Plain MMA (last tile / edge-adjacent): 4 k-steps of 16
#define MMA_PLAIN(buf_) { _Pragma("unroll") \
    for (int q = 0; q < 4; q++) { \
        uint32_t afr[4][4], bfr[4][4]; \
        _Pragma("unroll") \
        for (int mf = 0; mf < 4; mf++) \
            ldsm4(sA[buf_] + aoff[mf] + swzA[q], afr[mf]); \
        _Pragma("unroll") \
        for (int n2 = 0; n2 < 4; n2++) \
            ldsm4(sW[buf_] + boff[n2] + swzB[q], bfr[n2]); \
        _Pragma("unroll") \
        for (int mf = 0; mf < 4; mf++) \
            _Pragma("unroll") \
            for (int nf = 0; nf < 8; nf++) \
                mma_f16(acc[mf][nf], afr[mf], &bfr[nf >> 1][(nf & 1) * 2]); } }

// Interleaved MMA: tile T's HMMA stream carries tile T+1's prep, one slice per
// 8-HMMA group. Even slots: LDS.128 b + cp16 W; odd slots: 4 HMUL2 + STS.128 A.
#define MMA_INTER(bufR_, av2_, wsrc_) { \
    uint32_t afr[4][4], bfr[4][4]; \
    uint32_t bq0__, bq1__, bq2__, bq3__; \
    _Pragma("unroll") \
    for (int mf = 0; mf < 4; mf++) \
        ldsm4(sA[bufR_] + aoff[mf] + swzA[0], afr[mf]); \
    _Pragma("unroll") \
    for (int n2 = 0; n2 < 4; n2++) \
        ldsm4(sW[bufR_] + boff[n2] + swzB[0], bfr[n2]); \
    _Pragma("unroll") \
    for (int q = 0; q < 4; q++) { \
        _Pragma("unroll") \
        for (int mf = 0; mf < 4; mf++) { \
            const int slot = q * 4 + mf; \
            const uint32_t w = (uint32_t)(slot >> 1); \
            if ((slot & 1) == 0) { \
                asm volatile("ld.shared.v4.b32 {%0,%1,%2,%3}, [%4];" \
                    : "=r"(bq0__), "=r"(bq1__), "=r"(bq2__), "=r"(bq3__) \
                    : "r"(sBH + genO + ((w ^ gsw) << 4))); \
                cp16(sW[(bufR_) ^ 1] + wO + ((w ^ gsw) << 4), (wsrc_) + w * 8); \
            } else { \
                uint32_t p0__ = hmul2(bq0__, av2_); \
                uint32_t p1__ = hmul2(bq1__, av2_); \
                uint32_t p2__ = hmul2(bq2__, av2_); \
                uint32_t p3__ = hmul2(bq3__, av2_); \
                asm volatile("st.shared.v4.b32 [%0], {%1,%2,%3,%4};" \
                    :: "r"(sA[(bufR_) ^ 1] + genO + ((w ^ gsw) << 4)), \
                       "r"(p0__), "r"(p1__), "r"(p2__), "r"(p3__) : "memory"); \
            } \
            _Pragma("unroll") \
            for (int nf = 0; nf < 8; nf++) \
                mma_f16(acc[mf][nf], afr[mf], &bfr[nf >> 1][(nf & 1) * 2]); \
        } \
        if (q < 3) { \
            _Pragma("unroll") \
            for (int mf = 0; mf < 4; mf++) \
                ldsm4(sA[bufR_] + aoff[mf] + swzA[q + 1], afr[mf]); \
            _Pragma("unroll") \
            for (int n2 = 0; n2 < 4; n2++) \
                ldsm4(sW[bufR_] + boff[n2] + swzB[q + 1], bfr[n2]); \
        } \
    } \
    asm volatile("cp.async.commit_group;"); }

    int t = start;
    while (t < end) {
        const int pos = t / TPP;
        const int pend = (pos + 1) * TPP < end ? (pos + 1) * TPP : end;
        const int ls = t - pos * TPP;
        const int le = pend - pos * TPP;
        const int m0 = (pos >> 1) * 128;
        const int n0 = (pos & 1) * 128;

        const float* aTb = g_aT + m0 + tid;
        const float* bTb = g_bT + m0 + tid;
        const char*  bhRow = (const char*)g_bh + (size_t)(m0 + tid) * 512;
        const __half* wRow = g_W1t + (size_t)(n0 + tid) * KP2H;
        const __half* eRow = g_W1e + (size_t)(n0 + tid) * 512;

#pragma unroll
        for (int mf = 0; mf < 4; mf++)
#pragma unroll
            for (int nf = 0; nf < 8; nf++)
#pragma unroll
                for (int e = 0; e < 4; e++) acc[mf][nf][e] = 0.0f;

        __syncthreads();  // protect buffers from lagging warps of prev segment

        // prologue: tile ls into buffer 0
        int jc_cur = -1;
        float av = 0.0f;
        if (ls < 1024) {
            jc_cur = ls >> 8;
            STAGEBH(jc_cur);
            av = __ldg(aTb + (size_t)(ls & 255) * B_SZ);
            GENA(0, av);
            CPW(0, ls & 255, jc_cur);
        } else {
            GENE(0, ls - 1024);
            CPWE(0, ls - 1024);
        }
        float av_pf = 0.0f;
        if (ls + 1 < le && ls + 1 < 1024)
            av_pf = __ldg(aTb + (size_t)((ls + 1) & 255) * B_SZ);

        int buf = 0;
        for (int T = ls; T < le; T++) {
            asm volatile("cp.async.wait_group 0;");
            __syncthreads();

            const int nt = T + 1;
            if (nt < le && nt < 1024) {
                // regular next tile: prep interleaved into this tile's MMA
                if ((nt >> 8) != jc_cur) {
                    jc_cur = nt >> 8;
                    STAGEBH(jc_cur);   // own rows only; wait_group 0 inside
                }
                const uint32_t av2 = pkh2(av_pf, av_pf);
                const __half* wsrc = wRow + (size_t)(nt & 255) * 256 + jc_cur * 64;
                if (nt + 1 < le && nt + 1 < 1024)
                    av_pf = __ldg(aTb + (size_t)((nt + 1) & 255) * B_SZ);
                MMA_INTER(buf, av2, wsrc);
            } else {
                if (nt < le) {  // next is an edge tile
                    GENE(buf ^ 1, nt - 1024);
                    CPWE(buf ^ 1, nt - 1024);
                }
                MMA_PLAIN(buf);
            }
            buf ^= 1;
        }

        // flush this position's contribution (RED)
#pragma unroll
        for (int mf = 0; mf < 4; mf++) {
            const int gm = m0 + wm * 64 + mf * 16 + (L >> 2);
#pragma unroll
            for (int nf = 0; nf < 8; nf++) {
                const int gn = n0 + wn * 64 + nf * 8 + 2 * (L & 3);
                float* p0 = g_acc + (size_t)gm * NN + gn;
                float* p1 = g_acc + (size_t)(gm + 8) * NN + gn;
                atomicAdd(p0,     acc[mf][nf][0]);
                atomicAdd(p0 + 1, acc[mf][nf][1]);
                atomicAdd(p1,     acc[mf][nf][2]);
                atomicAdd(p1 + 1, acc[mf][nf][3]);
            }
        }

        t = pend;
    }
}

// ================================================================================
// Reduce: g_acc + leftover edge column (ke=512 -> i=256,j=255) + b1 + relu -> h,
// then layer2 FFMA2 + b2 + relu. 256 CTAs x 16 rows.
// ================================================================================
__global__ void __launch_bounds__(256) reduce_l2(
    const float* __restrict__ W1, const float* __restrict__ b1,
    const float* __restrict__ W2, const float* __restrict__ b2,
    float* __restrict__ out) {
    __shared__ float h_t[256 * 18];  // h transposed: h_t[k][m], stride 18
    const int m0 = blockIdx.x * 16;
    const int n  = threadIdx.x;

    const float bb1 = __ldg(b1 + n);
    // leftover edge term: fusion[m, 256*257+255] = b[m,255]; weight row 66047
    const float wlast = __ldg(W1 + (size_t)66047 * NN + n);
#pragma unroll
    for (int q = 0; q < 16; q++) {
        const float blast = __ldg(g_bT + (size_t)255 * B_SZ + m0 + q);
        float sum = fmaf(blast, wlast, bb1) + g_acc[(size_t)(m0 + q) * NN + n];
        h_t[n * 18 + q] = fmaxf(sum, 0.0f);
    }
    __syncthreads();

    unsigned long long acc[8];
#pragma unroll
    for (int mp = 0; mp < 8; mp++) acc[mp] = 0ull;

#pragma unroll 4
    for (int k = 0; k < NN; k++) {
        const unsigned long long wp = pk1(__ldg(W2 + (size_t)k * NN + n));
        const float* hk = &h_t[k * 18];
#pragma unroll
        for (int mp = 0; mp < 8; mp++) {
            unsigned long long hv = *(const unsigned long long*)(hk + 2 * mp);
            acc[mp] = ffma2(hv, wp, acc[mp]);
        }
    }

    const float bb2 = __ldg(b2 + n);
#pragma unroll
    for (int mp = 0; mp < 8; mp++) {
        float x, y;
        upk(acc[mp], x, y);
        out[(size_t)(m0 + 2 * mp) * NN + n]     = fmaxf(x + bb2, 0.0f);
        out[(size_t)(m0 + 2 * mp + 1) * NN + n] = fmaxf(y + bb2, 0.0f);
    }
}

// ================================================================================
extern "C" void kernel_launch(void* const* d_in, const int* in_sizes, int n_in,
                              void* d_out, int out_size) {
    const float* inp1 = (const float*)d_in[0];
    const float* inp2 = (const float*)d_in[1];
    const float* W1   = (const float*)d_in[2];
    const float* b1   = (const float*)d_in[3];
    const float* W2   = (const float*)d_in[4];
    const float* b2   = (const float*)d_in[5];
    float* out = (float*)d_out;

    cudaFuncSetAttribute(mma_main, cudaFuncAttributeMaxDynamicSharedMemorySize, 81920);

    prep_inputs<<<dim3(128, 8, 2), 256>>>(inp1, inp2);   // also zeroes g_acc
    prep_bh<<<B_SZ, 128>>>(inp2);
    prep_w1<<<dim3(256, 4, 8), 256>>>(W1);
    prep_w1e<<<dim3(16, 8), 256>>>(W1);
    mma_main<<<NCTA, 128, 81920>>>();
    reduce_l2<<<B_SZ / 16, 256>>>(W1, b1, W2, b2, out);
}